// round 1
// baseline (speedup 1.0000x reference)
#include <cuda_runtime.h>
#include <math.h>

#define N_NODES 50000
#define N_EDGES 320000
#define R_REL   3
#define IN_DIM  768
#define HID     256
#define OUT_DIM 64
#define NEG_SLOPE 0.2f

// ---------------- static scratch (no allocations allowed) ----------------
__device__ float g_h  [(size_t)N_NODES * HID];             // 51.2 MB
__device__ float g_h2 [(size_t)N_NODES * HID];             // 51.2 MB
__device__ float g_xw [(size_t)R_REL * N_NODES * HID];     // 153.6 MB
__device__ float g_sq [R_REL * N_NODES];
__device__ float g_sk [R_REL * N_NODES];
__device__ float g_alpha[N_EDGES];
__device__ float g_m    [N_NODES];
__device__ float g_denom[N_NODES];
__device__ float g_t  [(size_t)N_NODES * OUT_DIM];

// ---------------- fp32 tiled GEMM: C = act(A[M,K] @ B[K,Nc] + bias) ------
// BM=128, BN=64, BK=16, 256 threads, 8x4 per thread. batched over blockIdx.z
// (B and C strided; A shared across batch).
template<bool RELU, bool HAS_BIAS>
__global__ __launch_bounds__(256)
void gemm128x64(const float* __restrict__ A, const float* __restrict__ B,
                const float* __restrict__ bias, float* __restrict__ C,
                int M, int K, int Nc, long long bStride, long long cStride)
{
    constexpr int BM = 128, BN = 64, BK = 16, TM = 8, TN = 4;
    B += (long long)blockIdx.z * bStride;
    C += (long long)blockIdx.z * cStride;

    const int tid  = threadIdx.x;      // 0..255
    const int row0 = blockIdx.y * BM;
    const int col0 = blockIdx.x * BN;
    const int trow = tid >> 4;         // 0..15
    const int tcol = tid & 15;         // 0..15

    __shared__ float As[BK][BM];       // transposed A tile
    __shared__ float Bs[BK][BN];

    float acc[TM][TN];
#pragma unroll
    for (int i = 0; i < TM; i++)
#pragma unroll
        for (int j = 0; j < TN; j++) acc[i][j] = 0.f;

    for (int k0 = 0; k0 < K; k0 += BK) {
        // --- load A tile: 128x16 = 512 float4 slots, 2 per thread ---
#pragma unroll
        for (int it = 0; it < 2; it++) {
            int idx = tid + it * 256;       // 0..511
            int m   = idx >> 2;             // 0..127
            int kq  = idx & 3;              // 0..3 (float4 group along K)
            float4 v = make_float4(0.f, 0.f, 0.f, 0.f);
            int gm = row0 + m;
            if (gm < M)
                v = *(const float4*)(A + (size_t)gm * K + k0 + kq * 4);
            As[kq*4+0][m] = v.x; As[kq*4+1][m] = v.y;
            As[kq*4+2][m] = v.z; As[kq*4+3][m] = v.w;
        }
        // --- load B tile: 16x64 = 256 float4 slots, 1 per thread ---
        {
            int kr = tid >> 4;              // 0..15
            int nq = tid & 15;              // 0..15
            float4 v = *(const float4*)(B + (size_t)(k0 + kr) * Nc + col0 + nq * 4);
            *(float4*)(&Bs[kr][nq * 4]) = v;
        }
        __syncthreads();

#pragma unroll
        for (int kk = 0; kk < BK; kk++) {
            float ra[TM], rb[TN];
            float4 a0 = *(const float4*)(&As[kk][trow * TM]);
            float4 a1 = *(const float4*)(&As[kk][trow * TM + 4]);
            ra[0]=a0.x; ra[1]=a0.y; ra[2]=a0.z; ra[3]=a0.w;
            ra[4]=a1.x; ra[5]=a1.y; ra[6]=a1.z; ra[7]=a1.w;
            float4 b0 = *(const float4*)(&Bs[kk][tcol * TN]);
            rb[0]=b0.x; rb[1]=b0.y; rb[2]=b0.z; rb[3]=b0.w;
#pragma unroll
            for (int i = 0; i < TM; i++)
#pragma unroll
                for (int j = 0; j < TN; j++)
                    acc[i][j] = fmaf(ra[i], rb[j], acc[i][j]);
        }
        __syncthreads();
    }

    // --- epilogue ---
#pragma unroll
    for (int i = 0; i < TM; i++) {
        int gm = row0 + trow * TM + i;
        if (gm >= M) continue;
        int gc = col0 + tcol * TN;
        float4 v = make_float4(acc[i][0], acc[i][1], acc[i][2], acc[i][3]);
        if (HAS_BIAS) {
            v.x += bias[gc+0]; v.y += bias[gc+1];
            v.z += bias[gc+2]; v.w += bias[gc+3];
        }
        if (RELU) {
            v.x = fmaxf(v.x, 0.f); v.y = fmaxf(v.y, 0.f);
            v.z = fmaxf(v.z, 0.f); v.w = fmaxf(v.w, 0.f);
        }
        *(float4*)(C + (size_t)gm * Nc + gc) = v;
    }
}

// ---------------- per-(relation,node) attention scalars ------------------
__global__ void sqk_kernel(const float* __restrict__ xw,
                           const float* __restrict__ q,
                           const float* __restrict__ k,
                           float* __restrict__ sq, float* __restrict__ sk)
{
    int warp = (blockIdx.x * blockDim.x + threadIdx.x) >> 5;
    int lane = threadIdx.x & 31;
    if (warp >= R_REL * N_NODES) return;
    const float* row = xw + (size_t)warp * HID;
    float aq = 0.f, ak = 0.f;
#pragma unroll
    for (int i = lane; i < HID; i += 32) {
        float v = row[i];
        aq = fmaf(v, q[i], aq);
        ak = fmaf(v, k[i], ak);
    }
#pragma unroll
    for (int o = 16; o; o >>= 1) {
        aq += __shfl_xor_sync(0xffffffffu, aq, o);
        ak += __shfl_xor_sync(0xffffffffu, ak, o);
    }
    if (lane == 0) { sq[warp] = aq; sk[warp] = ak; }
}

// ---------------- init: out rows = bias, m = -inf, denom = 0 -------------
__global__ void init_kernel(float* __restrict__ out, const float* __restrict__ bias,
                            float* __restrict__ m, float* __restrict__ denom)
{
    int idx = blockIdx.x * blockDim.x + threadIdx.x;
    if (idx < N_NODES * HID) out[idx] = bias[idx & (HID - 1)];
    if (idx < N_NODES) { m[idx] = -INFINITY; denom[idx] = 0.f; }
}

__device__ __forceinline__ void atomicMaxF(float* addr, float val)
{
    int old = __float_as_int(*addr);
    while (__int_as_float(old) < val) {
        int assumed = old;
        old = atomicCAS((int*)addr, assumed, __float_as_int(val));
        if (old == assumed) break;
    }
}

// ---------------- edge pass 1: alpha = leaky_relu(sq[d]+sk[s]); max ------
__global__ void alpha_kernel(const float* __restrict__ sq, const float* __restrict__ sk,
                             const int* __restrict__ src, const int* __restrict__ dst,
                             const int* __restrict__ et,
                             float* __restrict__ alpha, float* __restrict__ m)
{
    int e = blockIdx.x * blockDim.x + threadIdx.x;
    if (e >= N_EDGES) return;
    int s = src[e], d = dst[e], r = et[e];
    float a = sq[r * N_NODES + d] + sk[r * N_NODES + s];
    a = (a > 0.f) ? a : NEG_SLOPE * a;
    alpha[e] = a;
    atomicMaxF(&m[d], a);
}

// ---------------- edge pass 2: ea = exp(alpha - m[d]); denom sum ---------
__global__ void ea_kernel(float* __restrict__ alpha, const float* __restrict__ m,
                          const int* __restrict__ dst, float* __restrict__ denom)
{
    int e = blockIdx.x * blockDim.x + threadIdx.x;
    if (e >= N_EDGES) return;
    int d = dst[e];
    float ea = expf(alpha[e] - m[d]);
    alpha[e] = ea;
    atomicAdd(&denom[d], ea);
}

// ---------------- edge pass 3: out[d,:] += coef * xw[r,s,:] --------------
// one warp per edge, 8 floats per lane via 2x float4 gather + 8 atomics
__global__ __launch_bounds__(256)
void scatter_kernel(const float* __restrict__ xw, const float* __restrict__ ea,
                    const float* __restrict__ denom,
                    const int* __restrict__ src, const int* __restrict__ dst,
                    const int* __restrict__ et, float* __restrict__ out)
{
    int e = (blockIdx.x * blockDim.x + threadIdx.x) >> 5;
    if (e >= N_EDGES) return;
    int lane = threadIdx.x & 31;
    int s = src[e], d = dst[e], r = et[e];
    float coef = ea[e] / (denom[d] + 1e-16f);
    const float4* xr = (const float4*)(xw + ((size_t)r * N_NODES + s) * HID);
    float* orow = out + (size_t)d * HID;
#pragma unroll
    for (int j = 0; j < 2; j++) {
        int q4 = lane + j * 32;            // 0..63 float4 index
        float4 v = xr[q4];
        int base = q4 * 4;
        atomicAdd(orow + base + 0, coef * v.x);
        atomicAdd(orow + base + 1, coef * v.y);
        atomicAdd(orow + base + 2, coef * v.z);
        atomicAdd(orow + base + 3, coef * v.w);
    }
}

// ---------------- classifier: out[n,c] = t[n,:] @ w_cls[:,c] + b_cls -----
__global__ void cls_kernel(const float* __restrict__ t, const float* __restrict__ w_cls,
                           const float* __restrict__ b_cls, float* __restrict__ out)
{
    int idx = blockIdx.x * blockDim.x + threadIdx.x;
    if (idx >= N_NODES * 2) return;
    int n = idx >> 1, c = idx & 1;
    const float* tr = t + (size_t)n * OUT_DIM;
    float acc = b_cls[c];
#pragma unroll
    for (int i = 0; i < OUT_DIM; i++)
        acc = fmaf(tr[i], w_cls[i * 2 + c], acc);
    out[idx] = acc;
}

// ---------------- host orchestration -------------------------------------
static void rgat_layer(const float* h_in, const float* W, const float* q,
                       const float* k, const float* bias, float* h_out,
                       const int* src, const int* dst, const int* et,
                       float* xw, float* sq, float* sk, float* alpha,
                       float* m, float* denom)
{
    // per-relation transform xw[r] = h_in @ W[r]
    gemm128x64<false, false><<<dim3(HID / 64, (N_NODES + 127) / 128, R_REL), 256>>>(
        h_in, W, nullptr, xw, N_NODES, HID, HID,
        (long long)HID * HID, (long long)N_NODES * HID);
    sqk_kernel<<<(R_REL * N_NODES * 32 + 255) / 256, 256>>>(xw, q, k, sq, sk);
    init_kernel<<<(N_NODES * HID + 255) / 256, 256>>>(h_out, bias, m, denom);
    alpha_kernel<<<(N_EDGES + 255) / 256, 256>>>(sq, sk, src, dst, et, alpha, m);
    ea_kernel<<<(N_EDGES + 255) / 256, 256>>>(alpha, m, dst, denom);
    scatter_kernel<<<(N_EDGES * 32 + 255) / 256, 256>>>(xw, alpha, denom, src, dst, et, h_out);
}

extern "C" void kernel_launch(void* const* d_in, const int* in_sizes, int n_in,
                              void* d_out, int out_size)
{
    const float* x          = (const float*)d_in[0];
    const int*   edge_index = (const int*)  d_in[1];
    const int*   edge_type  = (const int*)  d_in[2];
    const float* w_in       = (const float*)d_in[3];
    const float* b_in       = (const float*)d_in[4];
    const float* c1w = (const float*)d_in[5];
    const float* c1q = (const float*)d_in[6];
    const float* c1k = (const float*)d_in[7];
    const float* c1b = (const float*)d_in[8];
    const float* c2w = (const float*)d_in[9];
    const float* c2q = (const float*)d_in[10];
    const float* c2k = (const float*)d_in[11];
    const float* c2b = (const float*)d_in[12];
    const float* w_out = (const float*)d_in[13];
    const float* b_out = (const float*)d_in[14];
    const float* w_cls = (const float*)d_in[15];
    const float* b_cls = (const float*)d_in[16];
    float* out = (float*)d_out;

    const int* src = edge_index;            // edge_index[0, :]
    const int* dst = edge_index + N_EDGES;  // edge_index[1, :]

    float *p_h, *p_h2, *p_xw, *p_sq, *p_sk, *p_alpha, *p_m, *p_denom, *p_t;
    cudaGetSymbolAddress((void**)&p_h,     g_h);
    cudaGetSymbolAddress((void**)&p_h2,    g_h2);
    cudaGetSymbolAddress((void**)&p_xw,    g_xw);
    cudaGetSymbolAddress((void**)&p_sq,    g_sq);
    cudaGetSymbolAddress((void**)&p_sk,    g_sk);
    cudaGetSymbolAddress((void**)&p_alpha, g_alpha);
    cudaGetSymbolAddress((void**)&p_m,     g_m);
    cudaGetSymbolAddress((void**)&p_denom, g_denom);
    cudaGetSymbolAddress((void**)&p_t,     g_t);

    // h = relu(x @ w_in + b_in)
    gemm128x64<true, true><<<dim3(HID / 64, (N_NODES + 127) / 128, 1), 256>>>(
        x, w_in, b_in, p_h, N_NODES, IN_DIM, HID, 0, 0);

    // conv1: g_h -> g_h2
    rgat_layer(p_h, c1w, c1q, c1k, c1b, p_h2, src, dst, edge_type,
               p_xw, p_sq, p_sk, p_alpha, p_m, p_denom);
    // conv2: g_h2 -> g_h
    rgat_layer(p_h2, c2w, c2q, c2k, c2b, p_h, src, dst, edge_type,
               p_xw, p_sq, p_sk, p_alpha, p_m, p_denom);

    // t = relu(h @ w_out + b_out)
    gemm128x64<true, true><<<dim3(OUT_DIM / 64, (N_NODES + 127) / 128, 1), 256>>>(
        p_h, w_out, b_out, p_t, N_NODES, HID, OUT_DIM, 0, 0);

    // out = t @ w_cls + b_cls
    cls_kernel<<<(N_NODES * 2 + 255) / 256, 256>>>(p_t, w_cls, b_cls, out);
}

// round 6
// speedup vs baseline: 2.3628x; 2.3628x over previous
#include <cuda_runtime.h>
#include <cuda_fp16.h>
#include <math.h>
#include <stdint.h>

#define N_NODES 50000
#define N_EDGES 320000
#define R_REL   3
#define IN_DIM  768
#define HID     256
#define OUT_DIM 64
#define NEG_SLOPE 0.2f

// ---------------- static scratch (no allocations allowed) ----------------
__device__ float  g_h2 [(size_t)N_NODES * HID];
__device__ float  g_h3 [(size_t)N_NODES * HID];
__device__ float  g_xw [(size_t)R_REL * N_NODES * HID];
__device__ float  g_sq [R_REL * N_NODES];
__device__ float  g_sk [R_REL * N_NODES];
__device__ float  g_alpha[N_EDGES];
__device__ float  g_m    [N_NODES];
__device__ float  g_denom[N_NODES];
__device__ float  g_t  [(size_t)N_NODES * OUT_DIM];
__device__ __half g_xh [(size_t)N_NODES * IN_DIM];
__device__ __half g_hh [(size_t)N_NODES * HID];
__device__ __half g_wt [IN_DIM * HID];                  // w_in^T  [256][768]
__device__ __half g_cwt[(size_t)R_REL * HID * HID];     // conv W^T [r][256][256]
__device__ __half g_wot[HID * OUT_DIM];                 // w_out^T [64][256]

// ================= baseline-ISA helpers (sm_80+ features only) ============
__device__ __forceinline__ uint32_t smem_u32(const void* p) {
    uint32_t a;
    asm("{ .reg .u64 t; cvta.to.shared.u64 t, %1; cvt.u32.u64 %0, t; }" : "=r"(a) : "l"(p));
    return a;
}
#define CP_ASYNC16(dst, src, sz) \
    asm volatile("cp.async.ca.shared.global [%0], [%1], 16, %2;" \
                 :: "r"(dst), "l"(src), "r"(sz))
#define CP_COMMIT() asm volatile("cp.async.commit_group;")
#define CP_WAIT(n)  asm volatile("cp.async.wait_group %0;" :: "n"(n))

__device__ __forceinline__ void ldsm_x4(uint32_t* r, uint32_t addr) {
    asm volatile("ldmatrix.sync.aligned.m8n8.x4.shared.b16 {%0,%1,%2,%3}, [%4];"
                 : "=r"(r[0]), "=r"(r[1]), "=r"(r[2]), "=r"(r[3]) : "r"(addr));
}
__device__ __forceinline__ void mma16816(float* d, const uint32_t* a,
                                         uint32_t b0, uint32_t b1) {
    asm volatile("mma.sync.aligned.m16n8k16.row.col.f32.f16.f16.f32 "
                 "{%0,%1,%2,%3}, {%4,%5,%6,%7}, {%8,%9}, {%0,%1,%2,%3};"
                 : "+f"(d[0]), "+f"(d[1]), "+f"(d[2]), "+f"(d[3])
                 : "r"(a[0]), "r"(a[1]), "r"(a[2]), "r"(a[3]), "r"(b0), "r"(b1));
}

// ================= HMMA GEMM ==============================================
// C[M, NTOT] = A[M, KTOT](fp16 row-major) @ Bt[NTOT, KTOT]^T (fp16 K-major)
// CTA tile 128 x CN, 8 warps (4 along M, 2 along N), warp tile 32 x CN/2.
// MODE 0: conv  — fp32 Cf (+z strides), fused sq/sk partial dots (atomicAdd)
// MODE 1: w_in  — bias + relu -> fp16 Ch
// MODE 2: w_out — bias + relu -> fp32 Cf
template<int KTOT, int NTOT, int CN, int MODE>
__global__ __launch_bounds__(256, 1)
void gemm_mma(const __half* __restrict__ A, const __half* __restrict__ Bt,
              const float* __restrict__ bias, const float* __restrict__ qv,
              const float* __restrict__ kv, float* __restrict__ Cf,
              __half* __restrict__ Ch, float* __restrict__ sq,
              float* __restrict__ sk, int M)
{
    constexpr int KT    = KTOT / 64;        // k-tiles
    constexpr int LDS   = 72;               // padded row stride (halves)
    constexpr int A_STG = 128 * LDS * 2;    // bytes per A stage
    constexpr int B_STG = CN * LDS * 2;
    constexpr int A_IT  = 128 * 8 / 256;    // 16B chunks per thread (A)
    constexpr int B_IT  = CN * 8 / 256;
    constexpr int WNSZ  = CN / 2;
    constexpr int NT    = WNSZ / 8;

    extern __shared__ char smem[];
    const uint32_t sb = smem_u32(smem);
    const int tid = threadIdx.x, wid = tid >> 5, lane = tid & 31;
    const int warp_m = wid & 3, warp_n = wid >> 2;
    const int row0 = blockIdx.x * 128;
    const int col0 = blockIdx.y * CN;
    const int z = blockIdx.z;
    const __half* Btz = Bt + (size_t)z * NTOT * KTOT;
    if (MODE == 0) { Cf += (size_t)z * M * NTOT; sq += (size_t)z * M; sk += (size_t)z * M; }

    float acc[2][NT][4];
#pragma unroll
    for (int mt = 0; mt < 2; mt++)
#pragma unroll
        for (int nt = 0; nt < NT; nt++)
#pragma unroll
            for (int j = 0; j < 4; j++) acc[mt][nt][j] = 0.f;

    auto prefetch = [&](int kb) {
        int buf = kb & 1;
        uint32_t abase = sb + buf * A_STG;
#pragma unroll
        for (int i = 0; i < A_IT; i++) {
            int q = tid + i * 256, r = q >> 3, c = q & 7;
            uint32_t dst = abase + (uint32_t)(r * LDS + c * 8) * 2;
            const void* src = A + (size_t)(row0 + r) * KTOT + kb * 64 + c * 8;
            CP_ASYNC16(dst, src, (row0 + r < M) ? 16 : 0);
        }
        uint32_t bbase = sb + 2 * A_STG + buf * B_STG;
#pragma unroll
        for (int i = 0; i < B_IT; i++) {
            int q = tid + i * 256, r = q >> 3, c = q & 7;
            uint32_t dst = bbase + (uint32_t)(r * LDS + c * 8) * 2;
            const void* src = Btz + (size_t)(col0 + r) * KTOT + kb * 64 + c * 8;
            CP_ASYNC16(dst, src, 16);
        }
        CP_COMMIT();
    };

    prefetch(0);
    for (int kb = 0; kb < KT; kb++) {
        if (kb + 1 < KT) { prefetch(kb + 1); CP_WAIT(1); }
        else             { CP_WAIT(0); }
        __syncthreads();

        int buf = kb & 1;
        uint32_t a_lane = sb + buf * A_STG +
            (uint32_t)((warp_m * 32 + (lane & 15)) * LDS + (lane >> 4) * 8) * 2;
        uint32_t b_lane = sb + 2 * A_STG + buf * B_STG +
            (uint32_t)((warp_n * WNSZ + (lane >> 4) * 8 + (lane & 7)) * LDS +
                       ((lane >> 3) & 1) * 8) * 2;
#pragma unroll
        for (int ks = 0; ks < 4; ks++) {
            uint32_t a[2][4];
            ldsm_x4(a[0], a_lane + ks * 32);
            ldsm_x4(a[1], a_lane + 16 * LDS * 2 + ks * 32);
            uint32_t b[NT / 2][4];
#pragma unroll
            for (int n2 = 0; n2 < NT / 2; n2++)
                ldsm_x4(b[n2], b_lane + n2 * 16 * LDS * 2 + ks * 32);
#pragma unroll
            for (int mt = 0; mt < 2; mt++)
#pragma unroll
                for (int nt = 0; nt < NT; nt++)
                    mma16816(acc[mt][nt], a[mt],
                             b[nt >> 1][(nt & 1) * 2], b[nt >> 1][(nt & 1) * 2 + 1]);
        }
        __syncthreads();
    }

    // ---------------- epilogue ----------------
    const int r_base = row0 + warp_m * 32 + (lane >> 2);
    const int c_base = col0 + warp_n * WNSZ + (lane & 3) * 2;
#pragma unroll
    for (int mt = 0; mt < 2; mt++) {
#pragma unroll
        for (int h = 0; h < 2; h++) {
            const int gm = r_base + mt * 16 + h * 8;
            if (MODE == 0) {
                float aq = 0.f, ak = 0.f;
#pragma unroll
                for (int nt = 0; nt < NT; nt++) {
                    int c = c_base + nt * 8;
                    float v0 = acc[mt][nt][h * 2 + 0];
                    float v1 = acc[mt][nt][h * 2 + 1];
                    if (gm < M)
                        *(float2*)(Cf + (size_t)gm * NTOT + c) = make_float2(v0, v1);
                    aq = fmaf(v0, __ldg(qv + c), fmaf(v1, __ldg(qv + c + 1), aq));
                    ak = fmaf(v0, __ldg(kv + c), fmaf(v1, __ldg(kv + c + 1), ak));
                }
                aq += __shfl_xor_sync(0xffffffffu, aq, 1);
                aq += __shfl_xor_sync(0xffffffffu, aq, 2);
                ak += __shfl_xor_sync(0xffffffffu, ak, 1);
                ak += __shfl_xor_sync(0xffffffffu, ak, 2);
                if ((lane & 3) == 0 && gm < M) {
                    atomicAdd(sq + gm, aq);
                    atomicAdd(sk + gm, ak);
                }
            } else if (MODE == 1) {
                if (gm < M) {
#pragma unroll
                    for (int nt = 0; nt < NT; nt++) {
                        int c = c_base + nt * 8;
                        float v0 = fmaxf(acc[mt][nt][h * 2 + 0] + __ldg(bias + c), 0.f);
                        float v1 = fmaxf(acc[mt][nt][h * 2 + 1] + __ldg(bias + c + 1), 0.f);
                        *(__half2*)(Ch + (size_t)gm * NTOT + c) = __floats2half2_rn(v0, v1);
                    }
                }
            } else {
                if (gm < M) {
#pragma unroll
                    for (int nt = 0; nt < NT; nt++) {
                        int c = c_base + nt * 8;
                        float v0 = fmaxf(acc[mt][nt][h * 2 + 0] + __ldg(bias + c), 0.f);
                        float v1 = fmaxf(acc[mt][nt][h * 2 + 1] + __ldg(bias + c + 1), 0.f);
                        *(float2*)(Cf + (size_t)gm * NTOT + c) = make_float2(v0, v1);
                    }
                }
            }
        }
    }
}

// ---------------- prep kernels --------------------------------------------
__global__ void transpose_wt(const float* __restrict__ in, __half* __restrict__ out,
                             int K, int N)  // in [K,N] -> out [N,K], batched over z
{
    size_t base = (size_t)blockIdx.z * K * N;
    int o = blockIdx.x * 256 + threadIdx.x;
    if (o >= K * N) return;
    int n = o / K, k = o % K;
    out[base + o] = __float2half(in[base + (size_t)k * N + n]);
}

__global__ void f2h4_kernel(const float4* __restrict__ in, __half2* __restrict__ out,
                            size_t n4)
{
    size_t i = (size_t)blockIdx.x * 256 + threadIdx.x;
    if (i >= n4) return;
    float4 v = in[i];
    out[2 * i]     = __floats2half2_rn(v.x, v.y);
    out[2 * i + 1] = __floats2half2_rn(v.z, v.w);
}

__global__ void zero_sqk(float* __restrict__ sq, float* __restrict__ sk)
{
    int i = blockIdx.x * 256 + threadIdx.x;
    if (i < R_REL * N_NODES) { sq[i] = 0.f; sk[i] = 0.f; }
}

// ---------------- edge phase kernels (from passing R1) --------------------
__global__ void init_kernel(float* __restrict__ out, const float* __restrict__ bias,
                            float* __restrict__ m, float* __restrict__ denom)
{
    int idx = blockIdx.x * blockDim.x + threadIdx.x;
    if (idx < N_NODES * HID) out[idx] = bias[idx & (HID - 1)];
    if (idx < N_NODES) { m[idx] = -INFINITY; denom[idx] = 0.f; }
}

__device__ __forceinline__ void atomicMaxF(float* addr, float val)
{
    int old = __float_as_int(*addr);
    while (__int_as_float(old) < val) {
        int assumed = old;
        old = atomicCAS((int*)addr, assumed, __float_as_int(val));
        if (old == assumed) break;
    }
}

__global__ void alpha_kernel(const float* __restrict__ sq, const float* __restrict__ sk,
                             const int* __restrict__ src, const int* __restrict__ dst,
                             const int* __restrict__ et,
                             float* __restrict__ alpha, float* __restrict__ m)
{
    int e = blockIdx.x * blockDim.x + threadIdx.x;
    if (e >= N_EDGES) return;
    int s = src[e], d = dst[e], r = et[e];
    float a = sq[r * N_NODES + d] + sk[r * N_NODES + s];
    a = (a > 0.f) ? a : NEG_SLOPE * a;
    alpha[e] = a;
    atomicMaxF(&m[d], a);
}

__global__ void ea_kernel(float* __restrict__ alpha, const float* __restrict__ m,
                          const int* __restrict__ dst, float* __restrict__ denom)
{
    int e = blockIdx.x * blockDim.x + threadIdx.x;
    if (e >= N_EDGES) return;
    int d = dst[e];
    float ea = expf(alpha[e] - m[d]);
    alpha[e] = ea;
    atomicAdd(&denom[d], ea);
}

__global__ __launch_bounds__(256)
void scatter_kernel(const float* __restrict__ xw, const float* __restrict__ ea,
                    const float* __restrict__ denom,
                    const int* __restrict__ src, const int* __restrict__ dst,
                    const int* __restrict__ et, float* __restrict__ out)
{
    int e = (blockIdx.x * blockDim.x + threadIdx.x) >> 5;
    if (e >= N_EDGES) return;
    int lane = threadIdx.x & 31;
    int s = src[e], d = dst[e], r = et[e];
    float coef = ea[e] / (denom[d] + 1e-16f);
    const float4* xr = (const float4*)(xw + ((size_t)r * N_NODES + s) * HID);
    float* orow = out + (size_t)d * HID;
#pragma unroll
    for (int j = 0; j < 2; j++) {
        int q4 = lane + j * 32;
        float4 v = xr[q4];
        int base = q4 * 4;
        atomicAdd(orow + base + 0, coef * v.x);
        atomicAdd(orow + base + 1, coef * v.y);
        atomicAdd(orow + base + 2, coef * v.z);
        atomicAdd(orow + base + 3, coef * v.w);
    }
}

__global__ void cls_kernel(const float* __restrict__ t, const float* __restrict__ w_cls,
                           const float* __restrict__ b_cls, float* __restrict__ out)
{
    int idx = blockIdx.x * blockDim.x + threadIdx.x;
    if (idx >= N_NODES * 2) return;
    int n = idx >> 1, c = idx & 1;
    const float* tr = t + (size_t)n * OUT_DIM;
    float acc = b_cls[c];
#pragma unroll
    for (int i = 0; i < OUT_DIM; i++)
        acc = fmaf(tr[i], w_cls[i * 2 + c], acc);
    out[idx] = acc;
}

// ---------------- host orchestration --------------------------------------
extern "C" void kernel_launch(void* const* d_in, const int* in_sizes, int n_in,
                              void* d_out, int out_size)
{
    const float* x          = (const float*)d_in[0];
    const int*   edge_index = (const int*)  d_in[1];
    const int*   edge_type  = (const int*)  d_in[2];
    const float* w_in  = (const float*)d_in[3];
    const float* b_in  = (const float*)d_in[4];
    const float* c1w = (const float*)d_in[5];
    const float* c1q = (const float*)d_in[6];
    const float* c1k = (const float*)d_in[7];
    const float* c1b = (const float*)d_in[8];
    const float* c2w = (const float*)d_in[9];
    const float* c2q = (const float*)d_in[10];
    const float* c2k = (const float*)d_in[11];
    const float* c2b = (const float*)d_in[12];
    const float* w_out = (const float*)d_in[13];
    const float* b_out = (const float*)d_in[14];
    const float* w_cls = (const float*)d_in[15];
    const float* b_cls = (const float*)d_in[16];
    float* out = (float*)d_out;

    const int* src = edge_index;
    const int* dst = edge_index + N_EDGES;

    float *p_h2, *p_h3, *p_xw, *p_sq, *p_sk, *p_al, *p_m, *p_dn, *p_t;
    __half *p_xh, *p_hh, *p_wt, *p_cwt, *p_wot;
    cudaGetSymbolAddress((void**)&p_h2,  g_h2);
    cudaGetSymbolAddress((void**)&p_h3,  g_h3);
    cudaGetSymbolAddress((void**)&p_xw,  g_xw);
    cudaGetSymbolAddress((void**)&p_sq,  g_sq);
    cudaGetSymbolAddress((void**)&p_sk,  g_sk);
    cudaGetSymbolAddress((void**)&p_al,  g_alpha);
    cudaGetSymbolAddress((void**)&p_m,   g_m);
    cudaGetSymbolAddress((void**)&p_dn,  g_denom);
    cudaGetSymbolAddress((void**)&p_t,   g_t);
    cudaGetSymbolAddress((void**)&p_xh,  g_xh);
    cudaGetSymbolAddress((void**)&p_hh,  g_hh);
    cudaGetSymbolAddress((void**)&p_wt,  g_wt);
    cudaGetSymbolAddress((void**)&p_cwt, g_cwt);
    cudaGetSymbolAddress((void**)&p_wot, g_wot);

    const int SMEM_BIG   = 73728;  // 2 stages * (128+128) rows * 144 B
    const int SMEM_SMALL = 55296;  // 2 stages * (128+64)  rows * 144 B
    cudaFuncSetAttribute((const void*)gemm_mma<768, 256, 128, 1>,
                         cudaFuncAttributeMaxDynamicSharedMemorySize, SMEM_BIG);
    cudaFuncSetAttribute((const void*)gemm_mma<256, 256, 128, 0>,
                         cudaFuncAttributeMaxDynamicSharedMemorySize, SMEM_BIG);
    cudaFuncSetAttribute((const void*)gemm_mma<256, 64, 64, 2>,
                         cudaFuncAttributeMaxDynamicSharedMemorySize, SMEM_SMALL);

    const int MB = (N_NODES + 127) / 128;   // 391

    // ---- prep: fp16 conversions + weight transposes ----
    f2h4_kernel<<<(int)(((size_t)N_NODES * IN_DIM / 4 + 255) / 256), 256>>>(
        (const float4*)x, (__half2*)p_xh, (size_t)N_NODES * IN_DIM / 4);
    transpose_wt<<<dim3((IN_DIM * HID + 255) / 256, 1, 1), 256>>>(w_in, p_wt, IN_DIM, HID);
    transpose_wt<<<dim3((HID * HID + 255) / 256, 1, R_REL), 256>>>(c1w, p_cwt, HID, HID);
    transpose_wt<<<dim3((HID * OUT_DIM + 255) / 256, 1, 1), 256>>>(w_out, p_wot, HID, OUT_DIM);

    // ---- h = relu(x @ w_in + b_in) -> fp16 ----
    gemm_mma<768, 256, 128, 1><<<dim3(MB, 2, 1), 256, SMEM_BIG>>>(
        p_xh, p_wt, b_in, nullptr, nullptr, nullptr, p_hh, nullptr, nullptr, N_NODES);

    // ---- conv1 ----
    zero_sqk<<<(R_REL * N_NODES + 255) / 256, 256>>>(p_sq, p_sk);
    gemm_mma<256, 256, 128, 0><<<dim3(MB, 2, R_REL), 256, SMEM_BIG>>>(
        p_hh, p_cwt, nullptr, c1q, c1k, p_xw, nullptr, p_sq, p_sk, N_NODES);
    init_kernel<<<(N_NODES * HID + 255) / 256, 256>>>(p_h2, c1b, p_m, p_dn);
    alpha_kernel<<<(N_EDGES + 255) / 256, 256>>>(p_sq, p_sk, src, dst, edge_type, p_al, p_m);
    ea_kernel<<<(N_EDGES + 255) / 256, 256>>>(p_al, p_m, dst, p_dn);
    scatter_kernel<<<(N_EDGES * 32 + 255) / 256, 256>>>(p_xw, p_al, p_dn, src, dst, edge_type, p_h2);
    f2h4_kernel<<<(int)(((size_t)N_NODES * HID / 4 + 255) / 256), 256>>>(
        (const float4*)p_h2, (__half2*)p_hh, (size_t)N_NODES * HID / 4);

    // ---- conv2 ----
    transpose_wt<<<dim3((HID * HID + 255) / 256, 1, R_REL), 256>>>(c2w, p_cwt, HID, HID);
    zero_sqk<<<(R_REL * N_NODES + 255) / 256, 256>>>(p_sq, p_sk);
    gemm_mma<256, 256, 128, 0><<<dim3(MB, 2, R_REL), 256, SMEM_BIG>>>(
        p_hh, p_cwt, nullptr, c2q, c2k, p_xw, nullptr, p_sq, p_sk, N_NODES);
    init_kernel<<<(N_NODES * HID + 255) / 256, 256>>>(p_h3, c2b, p_m, p_dn);
    alpha_kernel<<<(N_EDGES + 255) / 256, 256>>>(p_sq, p_sk, src, dst, edge_type, p_al, p_m);
    ea_kernel<<<(N_EDGES + 255) / 256, 256>>>(p_al, p_m, dst, p_dn);
    scatter_kernel<<<(N_EDGES * 32 + 255) / 256, 256>>>(p_xw, p_al, p_dn, src, dst, edge_type, p_h3);
    f2h4_kernel<<<(int)(((size_t)N_NODES * HID / 4 + 255) / 256), 256>>>(
        (const float4*)p_h3, (__half2*)p_hh, (size_t)N_NODES * HID / 4);

    // ---- head: t = relu(h @ w_out + b_out); out = t @ w_cls + b_cls ----
    gemm_mma<256, 64, 64, 2><<<dim3(MB, 1, 1), 256, SMEM_SMALL>>>(
        p_hh, p_wot, b_out, nullptr, nullptr, p_t, nullptr, nullptr, nullptr, N_NODES);
    cls_kernel<<<(N_NODES * 2 + 255) / 256, 256>>>(p_t, w_cls, b_cls, out);
}

// round 7
// speedup vs baseline: 4.2453x; 1.7967x over previous
#include <cuda_runtime.h>
#include <cuda_fp16.h>
#include <math.h>
#include <stdint.h>

#define N_NODES 50000
#define N_EDGES 320000
#define R_REL   3
#define IN_DIM  768
#define HID     256
#define OUT_DIM 64
#define NEG_SLOPE 0.2f
#define NBLK_SCAN 196   // ceil(N_NODES/256)

// ---------------- static scratch (no allocations allowed) ----------------
__device__ float  g_xw [(size_t)R_REL * N_NODES * HID];
__device__ float  g_sq [R_REL * N_NODES];
__device__ float  g_sk [R_REL * N_NODES];
__device__ float  g_t  [(size_t)N_NODES * OUT_DIM];
__device__ __half g_xh [(size_t)N_NODES * IN_DIM];
__device__ __half g_hh [(size_t)N_NODES * HID];
__device__ __half g_wt [IN_DIM * HID];                  // w_in^T  [256][768]
__device__ __half g_cwt[(size_t)R_REL * HID * HID];     // conv W^T [r][256][256]
__device__ __half g_wot[HID * OUT_DIM];                 // w_out^T [64][256]
// CSR scratch
__device__ int g_deg  [N_NODES];
__device__ int g_excl [N_NODES];
__device__ int g_bsum [256];
__device__ int g_rowptr[N_NODES + 1];
__device__ int g_fill [N_NODES];
__device__ int g_eidx [N_EDGES];        // packed (et<<16)|src, sorted by dst

// ================= baseline-ISA helpers (sm_80+ features only) ============
__device__ __forceinline__ uint32_t smem_u32(const void* p) {
    uint32_t a;
    asm("{ .reg .u64 t; cvta.to.shared.u64 t, %1; cvt.u32.u64 %0, t; }" : "=r"(a) : "l"(p));
    return a;
}
#define CP_ASYNC16(dst, src, sz) \
    asm volatile("cp.async.ca.shared.global [%0], [%1], 16, %2;" \
                 :: "r"(dst), "l"(src), "r"(sz))
#define CP_COMMIT() asm volatile("cp.async.commit_group;")
#define CP_WAIT(n)  asm volatile("cp.async.wait_group %0;" :: "n"(n))

__device__ __forceinline__ void ldsm_x4(uint32_t* r, uint32_t addr) {
    asm volatile("ldmatrix.sync.aligned.m8n8.x4.shared.b16 {%0,%1,%2,%3}, [%4];"
                 : "=r"(r[0]), "=r"(r[1]), "=r"(r[2]), "=r"(r[3]) : "r"(addr));
}
__device__ __forceinline__ void mma16816(float* d, const uint32_t* a,
                                         uint32_t b0, uint32_t b1) {
    asm volatile("mma.sync.aligned.m16n8k16.row.col.f32.f16.f16.f32 "
                 "{%0,%1,%2,%3}, {%4,%5,%6,%7}, {%8,%9}, {%0,%1,%2,%3};"
                 : "+f"(d[0]), "+f"(d[1]), "+f"(d[2]), "+f"(d[3])
                 : "r"(a[0]), "r"(a[1]), "r"(a[2]), "r"(a[3]), "r"(b0), "r"(b1));
}

// ================= HMMA GEMM (unchanged from R6) ==========================
template<int KTOT, int NTOT, int CN, int MODE>
__global__ __launch_bounds__(256, 1)
void gemm_mma(const __half* __restrict__ A, const __half* __restrict__ Bt,
              const float* __restrict__ bias, const float* __restrict__ qv,
              const float* __restrict__ kv, float* __restrict__ Cf,
              __half* __restrict__ Ch, float* __restrict__ sq,
              float* __restrict__ sk, int M)
{
    constexpr int KT    = KTOT / 64;
    constexpr int LDS   = 72;
    constexpr int A_STG = 128 * LDS * 2;
    constexpr int B_STG = CN * LDS * 2;
    constexpr int A_IT  = 128 * 8 / 256;
    constexpr int B_IT  = CN * 8 / 256;
    constexpr int WNSZ  = CN / 2;
    constexpr int NT    = WNSZ / 8;

    extern __shared__ char smem[];
    const uint32_t sb = smem_u32(smem);
    const int tid = threadIdx.x, wid = tid >> 5, lane = tid & 31;
    const int warp_m = wid & 3, warp_n = wid >> 2;
    const int row0 = blockIdx.x * 128;
    const int col0 = blockIdx.y * CN;
    const int z = blockIdx.z;
    const __half* Btz = Bt + (size_t)z * NTOT * KTOT;
    if (MODE == 0) { Cf += (size_t)z * M * NTOT; sq += (size_t)z * M; sk += (size_t)z * M; }

    float acc[2][NT][4];
#pragma unroll
    for (int mt = 0; mt < 2; mt++)
#pragma unroll
        for (int nt = 0; nt < NT; nt++)
#pragma unroll
            for (int j = 0; j < 4; j++) acc[mt][nt][j] = 0.f;

    auto prefetch = [&](int kb) {
        int buf = kb & 1;
        uint32_t abase = sb + buf * A_STG;
#pragma unroll
        for (int i = 0; i < A_IT; i++) {
            int q = tid + i * 256, r = q >> 3, c = q & 7;
            uint32_t dst = abase + (uint32_t)(r * LDS + c * 8) * 2;
            const void* src = A + (size_t)(row0 + r) * KTOT + kb * 64 + c * 8;
            CP_ASYNC16(dst, src, (row0 + r < M) ? 16 : 0);
        }
        uint32_t bbase = sb + 2 * A_STG + buf * B_STG;
#pragma unroll
        for (int i = 0; i < B_IT; i++) {
            int q = tid + i * 256, r = q >> 3, c = q & 7;
            uint32_t dst = bbase + (uint32_t)(r * LDS + c * 8) * 2;
            const void* src = Btz + (size_t)(col0 + r) * KTOT + kb * 64 + c * 8;
            CP_ASYNC16(dst, src, 16);
        }
        CP_COMMIT();
    };

    prefetch(0);
    for (int kb = 0; kb < KT; kb++) {
        if (kb + 1 < KT) { prefetch(kb + 1); CP_WAIT(1); }
        else             { CP_WAIT(0); }
        __syncthreads();

        int buf = kb & 1;
        uint32_t a_lane = sb + buf * A_STG +
            (uint32_t)((warp_m * 32 + (lane & 15)) * LDS + (lane >> 4) * 8) * 2;
        uint32_t b_lane = sb + 2 * A_STG + buf * B_STG +
            (uint32_t)((warp_n * WNSZ + (lane >> 4) * 8 + (lane & 7)) * LDS +
                       ((lane >> 3) & 1) * 8) * 2;
#pragma unroll
        for (int ks = 0; ks < 4; ks++) {
            uint32_t a[2][4];
            ldsm_x4(a[0], a_lane + ks * 32);
            ldsm_x4(a[1], a_lane + 16 * LDS * 2 + ks * 32);
            uint32_t b[NT / 2][4];
#pragma unroll
            for (int n2 = 0; n2 < NT / 2; n2++)
                ldsm_x4(b[n2], b_lane + n2 * 16 * LDS * 2 + ks * 32);
#pragma unroll
            for (int mt = 0; mt < 2; mt++)
#pragma unroll
                for (int nt = 0; nt < NT; nt++)
                    mma16816(acc[mt][nt], a[mt],
                             b[nt >> 1][(nt & 1) * 2], b[nt >> 1][(nt & 1) * 2 + 1]);
        }
        __syncthreads();
    }

    const int r_base = row0 + warp_m * 32 + (lane >> 2);
    const int c_base = col0 + warp_n * WNSZ + (lane & 3) * 2;
#pragma unroll
    for (int mt = 0; mt < 2; mt++) {
#pragma unroll
        for (int h = 0; h < 2; h++) {
            const int gm = r_base + mt * 16 + h * 8;
            if (MODE == 0) {
                float aq = 0.f, ak = 0.f;
#pragma unroll
                for (int nt = 0; nt < NT; nt++) {
                    int c = c_base + nt * 8;
                    float v0 = acc[mt][nt][h * 2 + 0];
                    float v1 = acc[mt][nt][h * 2 + 1];
                    if (gm < M)
                        *(float2*)(Cf + (size_t)gm * NTOT + c) = make_float2(v0, v1);
                    aq = fmaf(v0, __ldg(qv + c), fmaf(v1, __ldg(qv + c + 1), aq));
                    ak = fmaf(v0, __ldg(kv + c), fmaf(v1, __ldg(kv + c + 1), ak));
                }
                aq += __shfl_xor_sync(0xffffffffu, aq, 1);
                aq += __shfl_xor_sync(0xffffffffu, aq, 2);
                ak += __shfl_xor_sync(0xffffffffu, ak, 1);
                ak += __shfl_xor_sync(0xffffffffu, ak, 2);
                if ((lane & 3) == 0 && gm < M) {
                    atomicAdd(sq + gm, aq);
                    atomicAdd(sk + gm, ak);
                }
            } else if (MODE == 1) {
                if (gm < M) {
#pragma unroll
                    for (int nt = 0; nt < NT; nt++) {
                        int c = c_base + nt * 8;
                        float v0 = fmaxf(acc[mt][nt][h * 2 + 0] + __ldg(bias + c), 0.f);
                        float v1 = fmaxf(acc[mt][nt][h * 2 + 1] + __ldg(bias + c + 1), 0.f);
                        *(__half2*)(Ch + (size_t)gm * NTOT + c) = __floats2half2_rn(v0, v1);
                    }
                }
            } else {
                if (gm < M) {
#pragma unroll
                    for (int nt = 0; nt < NT; nt++) {
                        int c = c_base + nt * 8;
                        float v0 = fmaxf(acc[mt][nt][h * 2 + 0] + __ldg(bias + c), 0.f);
                        float v1 = fmaxf(acc[mt][nt][h * 2 + 1] + __ldg(bias + c + 1), 0.f);
                        *(float2*)(Cf + (size_t)gm * NTOT + c) = make_float2(v0, v1);
                    }
                }
            }
        }
    }
}

// ---------------- prep kernels --------------------------------------------
__global__ void transpose_wt(const float* __restrict__ in, __half* __restrict__ out,
                             int K, int N)
{
    size_t base = (size_t)blockIdx.z * K * N;
    int o = blockIdx.x * 256 + threadIdx.x;
    if (o >= K * N) return;
    int n = o / K, k = o % K;
    out[base + o] = __float2half(in[base + (size_t)k * N + n]);
}

__global__ void f2h4_kernel(const float4* __restrict__ in, __half2* __restrict__ out,
                            size_t n4)
{
    size_t i = (size_t)blockIdx.x * 256 + threadIdx.x;
    if (i >= n4) return;
    float4 v = in[i];
    out[2 * i]     = __floats2half2_rn(v.x, v.y);
    out[2 * i + 1] = __floats2half2_rn(v.z, v.w);
}

__global__ void zero_sqk(float* __restrict__ sq, float* __restrict__ sk)
{
    int i = blockIdx.x * 256 + threadIdx.x;
    if (i < R_REL * N_NODES) { sq[i] = 0.f; sk[i] = 0.f; }
}

// ---------------- CSR build ------------------------------------------------
__global__ void csr_zero(int* __restrict__ deg)
{
    int i = blockIdx.x * 256 + threadIdx.x;
    if (i < N_NODES) deg[i] = 0;
}
__global__ void csr_hist(const int* __restrict__ dst, int* __restrict__ deg)
{
    int e = blockIdx.x * 256 + threadIdx.x;
    if (e < N_EDGES) atomicAdd(&deg[dst[e]], 1);
}
__global__ void csr_scan1(const int* __restrict__ deg, int* __restrict__ excl,
                          int* __restrict__ bsum)
{
    __shared__ int sm[256];
    int t = threadIdx.x, i = blockIdx.x * 256 + t;
    int v = (i < N_NODES) ? deg[i] : 0;
    sm[t] = v;
    __syncthreads();
    for (int off = 1; off < 256; off <<= 1) {
        int x = (t >= off) ? sm[t - off] : 0;
        __syncthreads();
        if (t >= off) sm[t] += x;
        __syncthreads();
    }
    if (i < N_NODES) excl[i] = sm[t] - v;
    if (t == 255) bsum[blockIdx.x] = sm[255];
}
__global__ void csr_scan2(int* __restrict__ bsum)   // single block
{
    __shared__ int sm[256];
    int t = threadIdx.x;
    int v = (t < NBLK_SCAN) ? bsum[t] : 0;
    sm[t] = v;
    __syncthreads();
    for (int off = 1; off < 256; off <<= 1) {
        int x = (t >= off) ? sm[t - off] : 0;
        __syncthreads();
        if (t >= off) sm[t] += x;
        __syncthreads();
    }
    if (t < NBLK_SCAN) bsum[t] = sm[t] - v;
}
__global__ void csr_scan3(const int* __restrict__ excl, const int* __restrict__ bsum,
                          int* __restrict__ rowptr, int* __restrict__ fill)
{
    int i = blockIdx.x * 256 + threadIdx.x;
    if (i < N_NODES) {
        int p = excl[i] + bsum[i >> 8];
        rowptr[i] = p;
        fill[i]   = p;
    }
    if (i == 0) rowptr[N_NODES] = N_EDGES;
}
__global__ void csr_scatter(const int* __restrict__ src, const int* __restrict__ dst,
                            const int* __restrict__ et, int* __restrict__ fill,
                            int* __restrict__ eidx)
{
    int e = blockIdx.x * 256 + threadIdx.x;
    if (e >= N_EDGES) return;
    int pos = atomicAdd(&fill[dst[e]], 1);
    eidx[pos] = src[e] | (et[e] << 16);
}

// ---------------- fused softmax-aggregate: one warp per dst node ----------
// out_h[d,:] = half( (sum_e exp(a_e - m) * xw[r_e, s_e, :]) / (sum_e exp(a_e-m) + eps) + bias )
__global__ __launch_bounds__(256)
void aggregate_kernel(const int* __restrict__ rowptr, const int* __restrict__ eidx,
                      const float* __restrict__ sq, const float* __restrict__ sk,
                      const float* __restrict__ xw, const float* __restrict__ bias,
                      __half* __restrict__ out_h)
{
    const int d    = blockIdx.x * 8 + (threadIdx.x >> 5);   // grid sized exactly
    const int lane = threadIdx.x & 31;
    const int start = rowptr[d], end = rowptr[d + 1];

    const int c0 = lane * 4;            // cols [c0, c0+4)
    const int c1 = 128 + lane * 4;      // cols [c1, c1+4)

    if (start == end) {                 // no in-edges: out = bias
        float4 b0 = *(const float4*)(bias + c0);
        float4 b1 = *(const float4*)(bias + c1);
        __half2 h0 = __floats2half2_rn(b0.x, b0.y), h1 = __floats2half2_rn(b0.z, b0.w);
        __half2 h2 = __floats2half2_rn(b1.x, b1.y), h3 = __floats2half2_rn(b1.z, b1.w);
        *(uint2*)(out_h + (size_t)d * HID + c0) =
            make_uint2(*(uint32_t*)&h0, *(uint32_t*)&h1);
        *(uint2*)(out_h + (size_t)d * HID + c1) =
            make_uint2(*(uint32_t*)&h2, *(uint32_t*)&h3);
        return;
    }

    // pass 1: segment max of leaky_relu scores
    float m = -INFINITY;
    for (int i = start + lane; i < end; i += 32) {
        int pk = eidx[i];
        int s = pk & 0xFFFF, r = pk >> 16;
        float a = __ldg(sq + r * N_NODES + d) + __ldg(sk + r * N_NODES + s);
        a = (a > 0.f) ? a : NEG_SLOPE * a;
        m = fmaxf(m, a);
    }
#pragma unroll
    for (int o = 16; o; o >>= 1) m = fmaxf(m, __shfl_xor_sync(0xffffffffu, m, o));

    // pass 2: gather + unnormalized accumulate, denom alongside
    float acc[8];
#pragma unroll
    for (int j = 0; j < 8; j++) acc[j] = 0.f;
    float dn = 0.f;

    for (int base = start; base < end; base += 32) {
        int i = base + lane;
        float ea = 0.f; int pk = 0;
        if (i < end) {
            pk = eidx[i];
            int s = pk & 0xFFFF, r = pk >> 16;
            float a = __ldg(sq + r * N_NODES + d) + __ldg(sk + r * N_NODES + s);
            a = (a > 0.f) ? a : NEG_SLOPE * a;
            ea = __expf(a - m);
        }
        dn += ea;
        int cnt = min(32, end - base);
        for (int l = 0; l < cnt; l++) {
            float coef = __shfl_sync(0xffffffffu, ea, l);
            int pkl    = __shfl_sync(0xffffffffu, pk, l);
            int s = pkl & 0xFFFF, r = pkl >> 16;
            const float4* row = (const float4*)(xw + ((size_t)r * N_NODES + s) * HID);
            float4 v0 = row[lane], v1 = row[32 + lane];
            acc[0] = fmaf(coef, v0.x, acc[0]); acc[1] = fmaf(coef, v0.y, acc[1]);
            acc[2] = fmaf(coef, v0.z, acc[2]); acc[3] = fmaf(coef, v0.w, acc[3]);
            acc[4] = fmaf(coef, v1.x, acc[4]); acc[5] = fmaf(coef, v1.y, acc[5]);
            acc[6] = fmaf(coef, v1.z, acc[6]); acc[7] = fmaf(coef, v1.w, acc[7]);
        }
    }
#pragma unroll
    for (int o = 16; o; o >>= 1) dn += __shfl_xor_sync(0xffffffffu, dn, o);
    float inv = 1.f / (dn + 1e-16f);

    float4 b0 = *(const float4*)(bias + c0);
    float4 b1 = *(const float4*)(bias + c1);
    __half2 h0 = __floats2half2_rn(fmaf(acc[0], inv, b0.x), fmaf(acc[1], inv, b0.y));
    __half2 h1 = __floats2half2_rn(fmaf(acc[2], inv, b0.z), fmaf(acc[3], inv, b0.w));
    __half2 h2 = __floats2half2_rn(fmaf(acc[4], inv, b1.x), fmaf(acc[5], inv, b1.y));
    __half2 h3 = __floats2half2_rn(fmaf(acc[6], inv, b1.z), fmaf(acc[7], inv, b1.w));
    *(uint2*)(out_h + (size_t)d * HID + c0) = make_uint2(*(uint32_t*)&h0, *(uint32_t*)&h1);
    *(uint2*)(out_h + (size_t)d * HID + c1) = make_uint2(*(uint32_t*)&h2, *(uint32_t*)&h3);
}

// ---------------- classifier ----------------------------------------------
__global__ void cls_kernel(const float* __restrict__ t, const float* __restrict__ w_cls,
                           const float* __restrict__ b_cls, float* __restrict__ out)
{
    int idx = blockIdx.x * blockDim.x + threadIdx.x;
    if (idx >= N_NODES * 2) return;
    int n = idx >> 1, c = idx & 1;
    const float* tr = t + (size_t)n * OUT_DIM;
    float acc = b_cls[c];
#pragma unroll
    for (int i = 0; i < OUT_DIM; i++)
        acc = fmaf(tr[i], w_cls[i * 2 + c], acc);
    out[idx] = acc;
}

// ---------------- host orchestration --------------------------------------
extern "C" void kernel_launch(void* const* d_in, const int* in_sizes, int n_in,
                              void* d_out, int out_size)
{
    const float* x          = (const float*)d_in[0];
    const int*   edge_index = (const int*)  d_in[1];
    const int*   edge_type  = (const int*)  d_in[2];
    const float* w_in  = (const float*)d_in[3];
    const float* b_in  = (const float*)d_in[4];
    const float* c1w = (const float*)d_in[5];
    const float* c1q = (const float*)d_in[6];
    const float* c1k = (const float*)d_in[7];
    const float* c1b = (const float*)d_in[8];
    const float* c2w = (const float*)d_in[9];
    const float* c2q = (const float*)d_in[10];
    const float* c2k = (const float*)d_in[11];
    const float* c2b = (const float*)d_in[12];
    const float* w_out = (const float*)d_in[13];
    const float* b_out = (const float*)d_in[14];
    const float* w_cls = (const float*)d_in[15];
    const float* b_cls = (const float*)d_in[16];
    float* out = (float*)d_out;

    const int* src = edge_index;
    const int* dst = edge_index + N_EDGES;

    float *p_xw, *p_sq, *p_sk, *p_t;
    __half *p_xh, *p_hh, *p_wt, *p_cwt, *p_wot;
    int *p_deg, *p_excl, *p_bsum, *p_rowptr, *p_fill, *p_eidx;
    cudaGetSymbolAddress((void**)&p_xw,  g_xw);
    cudaGetSymbolAddress((void**)&p_sq,  g_sq);
    cudaGetSymbolAddress((void**)&p_sk,  g_sk);
    cudaGetSymbolAddress((void**)&p_t,   g_t);
    cudaGetSymbolAddress((void**)&p_xh,  g_xh);
    cudaGetSymbolAddress((void**)&p_hh,  g_hh);
    cudaGetSymbolAddress((void**)&p_wt,  g_wt);
    cudaGetSymbolAddress((void**)&p_cwt, g_cwt);
    cudaGetSymbolAddress((void**)&p_wot, g_wot);
    cudaGetSymbolAddress((void**)&p_deg,    g_deg);
    cudaGetSymbolAddress((void**)&p_excl,   g_excl);
    cudaGetSymbolAddress((void**)&p_bsum,   g_bsum);
    cudaGetSymbolAddress((void**)&p_rowptr, g_rowptr);
    cudaGetSymbolAddress((void**)&p_fill,   g_fill);
    cudaGetSymbolAddress((void**)&p_eidx,   g_eidx);

    const int SMEM_BIG   = 73728;
    const int SMEM_SMALL = 55296;
    cudaFuncSetAttribute((const void*)gemm_mma<768, 256, 128, 1>,
                         cudaFuncAttributeMaxDynamicSharedMemorySize, SMEM_BIG);
    cudaFuncSetAttribute((const void*)gemm_mma<256, 256, 128, 0>,
                         cudaFuncAttributeMaxDynamicSharedMemorySize, SMEM_BIG);
    cudaFuncSetAttribute((const void*)gemm_mma<256, 64, 64, 2>,
                         cudaFuncAttributeMaxDynamicSharedMemorySize, SMEM_SMALL);

    const int MB = (N_NODES + 127) / 128;   // 391
    const int EB = (N_EDGES + 255) / 256;   // 1250
    const int NB = (N_NODES + 255) / 256;   // 196

    // ---- CSR build (shared by both conv layers) ----
    csr_zero   <<<NB, 256>>>(p_deg);
    csr_hist   <<<EB, 256>>>(dst, p_deg);
    csr_scan1  <<<NB, 256>>>(p_deg, p_excl, p_bsum);
    csr_scan2  <<<1, 256>>>(p_bsum);
    csr_scan3  <<<NB, 256>>>(p_excl, p_bsum, p_rowptr, p_fill);
    csr_scatter<<<EB, 256>>>(src, dst, edge_type, p_fill, p_eidx);

    // ---- prep: fp16 conversions + weight transposes ----
    f2h4_kernel<<<(int)(((size_t)N_NODES * IN_DIM / 4 + 255) / 256), 256>>>(
        (const float4*)x, (__half2*)p_xh, (size_t)N_NODES * IN_DIM / 4);
    transpose_wt<<<dim3((IN_DIM * HID + 255) / 256, 1, 1), 256>>>(w_in, p_wt, IN_DIM, HID);
    transpose_wt<<<dim3((HID * HID + 255) / 256, 1, R_REL), 256>>>(c1w, p_cwt, HID, HID);
    transpose_wt<<<dim3((HID * OUT_DIM + 255) / 256, 1, 1), 256>>>(w_out, p_wot, HID, OUT_DIM);

    // ---- h = relu(x @ w_in + b_in) -> fp16 ----
    gemm_mma<768, 256, 128, 1><<<dim3(MB, 2, 1), 256, SMEM_BIG>>>(
        p_xh, p_wt, b_in, nullptr, nullptr, nullptr, p_hh, nullptr, nullptr, N_NODES);

    // ---- conv1: GEMM (+fused sq/sk) then fused softmax-aggregate -> fp16 hh
    zero_sqk<<<(R_REL * N_NODES + 255) / 256, 256>>>(p_sq, p_sk);
    gemm_mma<256, 256, 128, 0><<<dim3(MB, 2, R_REL), 256, SMEM_BIG>>>(
        p_hh, p_cwt, nullptr, c1q, c1k, p_xw, nullptr, p_sq, p_sk, N_NODES);
    aggregate_kernel<<<N_NODES / 8, 256>>>(p_rowptr, p_eidx, p_sq, p_sk, p_xw, c1b, p_hh);

    // ---- conv2 ----
    transpose_wt<<<dim3((HID * HID + 255) / 256, 1, R_REL), 256>>>(c2w, p_cwt, HID, HID);
    zero_sqk<<<(R_REL * N_NODES + 255) / 256, 256>>>(p_sq, p_sk);
    gemm_mma<256, 256, 128, 0><<<dim3(MB, 2, R_REL), 256, SMEM_BIG>>>(
        p_hh, p_cwt, nullptr, c2q, c2k, p_xw, nullptr, p_sq, p_sk, N_NODES);
    aggregate_kernel<<<N_NODES / 8, 256>>>(p_rowptr, p_eidx, p_sq, p_sk, p_xw, c2b, p_hh);

    // ---- head: t = relu(h @ w_out + b_out); out = t @ w_cls + b_cls ----
    gemm_mma<256, 64, 64, 2><<<dim3(MB, 1, 1), 256, SMEM_SMALL>>>(
        p_hh, p_wot, b_out, nullptr, nullptr, p_t, nullptr, nullptr, nullptr, N_NODES);
    cls_kernel<<<(N_NODES * 2 + 255) / 256, 256>>>(p_t, w_cls, b_cls, out);
}

// round 8
// speedup vs baseline: 4.9183x; 1.1585x over previous
#include <cuda_runtime.h>
#include <cuda_fp16.h>
#include <math.h>
#include <stdint.h>

#define N_NODES 50000
#define N_EDGES 320000
#define R_REL   3
#define IN_DIM  768
#define HID     256
#define OUT_DIM 64
#define NEG_SLOPE 0.2f
#define NBLK_SCAN 196   // ceil(N_NODES/256)

// ---------------- static scratch (no allocations allowed) ----------------
__device__ __half g_xwh[(size_t)R_REL * N_NODES * HID];   // fp16 per-relation transforms (75 MB)
__device__ float  g_sq [R_REL * N_NODES];
__device__ float  g_sk [R_REL * N_NODES];
__device__ __half g_xh [(size_t)N_NODES * IN_DIM];
__device__ __half g_hh [(size_t)N_NODES * HID];
__device__ __half g_wt [IN_DIM * HID];                  // w_in^T  [256][768]
__device__ __half g_cwt[(size_t)R_REL * HID * HID];     // conv W^T [r][256][256]
__device__ __half g_wot[HID * OUT_DIM];                 // w_out^T [64][256]
// CSR scratch
__device__ int g_deg  [N_NODES];
__device__ int g_excl [N_NODES];
__device__ int g_bsum [256];
__device__ int g_rowptr[N_NODES + 1];
__device__ int g_fill [N_NODES];
__device__ int g_eidx [N_EDGES];        // packed (et<<16)|src, sorted by dst

// ================= baseline-ISA helpers (sm_80+ features only) ============
__device__ __forceinline__ uint32_t smem_u32(const void* p) {
    uint32_t a;
    asm("{ .reg .u64 t; cvta.to.shared.u64 t, %1; cvt.u32.u64 %0, t; }" : "=r"(a) : "l"(p));
    return a;
}
#define CP_ASYNC16(dst, src, sz) \
    asm volatile("cp.async.ca.shared.global [%0], [%1], 16, %2;" \
                 :: "r"(dst), "l"(src), "r"(sz))
#define CP_COMMIT() asm volatile("cp.async.commit_group;")
#define CP_WAIT(n)  asm volatile("cp.async.wait_group %0;" :: "n"(n))

__device__ __forceinline__ void ldsm_x4(uint32_t* r, uint32_t addr) {
    asm volatile("ldmatrix.sync.aligned.m8n8.x4.shared.b16 {%0,%1,%2,%3}, [%4];"
                 : "=r"(r[0]), "=r"(r[1]), "=r"(r[2]), "=r"(r[3]) : "r"(addr));
}
__device__ __forceinline__ void mma16816(float* d, const uint32_t* a,
                                         uint32_t b0, uint32_t b1) {
    asm volatile("mma.sync.aligned.m16n8k16.row.col.f32.f16.f16.f32 "
                 "{%0,%1,%2,%3}, {%4,%5,%6,%7}, {%8,%9}, {%0,%1,%2,%3};"
                 : "+f"(d[0]), "+f"(d[1]), "+f"(d[2]), "+f"(d[3])
                 : "r"(a[0]), "r"(a[1]), "r"(a[2]), "r"(a[3]), "r"(b0), "r"(b1));
}

// ================= HMMA GEMM ==============================================
// MODE 0: conv  — fp16 Ch (= xwh, +z strides), fused sq/sk dots (atomicAdd)
// MODE 1: w_in  — bias + relu -> fp16 Ch
// MODE 2: head  — bias + relu + fused classifier -> atomicAdd into Cf(out)
//                 (qv = w_cls [64,2]; out must be pre-initialized to b_cls)
template<int KTOT, int NTOT, int CN, int MODE>
__global__ __launch_bounds__(256, 1)
void gemm_mma(const __half* __restrict__ A, const __half* __restrict__ Bt,
              const float* __restrict__ bias, const float* __restrict__ qv,
              const float* __restrict__ kv, float* __restrict__ Cf,
              __half* __restrict__ Ch, float* __restrict__ sq,
              float* __restrict__ sk, int M)
{
    constexpr int KT    = KTOT / 64;
    constexpr int LDS   = 72;
    constexpr int A_STG = 128 * LDS * 2;
    constexpr int B_STG = CN * LDS * 2;
    constexpr int A_IT  = 128 * 8 / 256;
    constexpr int B_IT  = CN * 8 / 256;
    constexpr int WNSZ  = CN / 2;
    constexpr int NT    = WNSZ / 8;

    extern __shared__ char smem[];
    const uint32_t sb = smem_u32(smem);
    const int tid = threadIdx.x, wid = tid >> 5, lane = tid & 31;
    const int warp_m = wid & 3, warp_n = wid >> 2;
    const int row0 = blockIdx.x * 128;
    const int col0 = blockIdx.y * CN;
    const int z = blockIdx.z;
    const __half* Btz = Bt + (size_t)z * NTOT * KTOT;
    if (MODE == 0) { Ch += (size_t)z * M * NTOT; sq += (size_t)z * M; sk += (size_t)z * M; }

    float acc[2][NT][4];
#pragma unroll
    for (int mt = 0; mt < 2; mt++)
#pragma unroll
        for (int nt = 0; nt < NT; nt++)
#pragma unroll
            for (int j = 0; j < 4; j++) acc[mt][nt][j] = 0.f;

    auto prefetch = [&](int kb) {
        int buf = kb & 1;
        uint32_t abase = sb + buf * A_STG;
#pragma unroll
        for (int i = 0; i < A_IT; i++) {
            int q = tid + i * 256, r = q >> 3, c = q & 7;
            uint32_t dst = abase + (uint32_t)(r * LDS + c * 8) * 2;
            const void* src = A + (size_t)(row0 + r) * KTOT + kb * 64 + c * 8;
            CP_ASYNC16(dst, src, (row0 + r < M) ? 16 : 0);
        }
        uint32_t bbase = sb + 2 * A_STG + buf * B_STG;
#pragma unroll
        for (int i = 0; i < B_IT; i++) {
            int q = tid + i * 256, r = q >> 3, c = q & 7;
            uint32_t dst = bbase + (uint32_t)(r * LDS + c * 8) * 2;
            const void* src = Btz + (size_t)(col0 + r) * KTOT + kb * 64 + c * 8;
            CP_ASYNC16(dst, src, 16);
        }
        CP_COMMIT();
    };

    prefetch(0);
    for (int kb = 0; kb < KT; kb++) {
        if (kb + 1 < KT) { prefetch(kb + 1); CP_WAIT(1); }
        else             { CP_WAIT(0); }
        __syncthreads();

        int buf = kb & 1;
        uint32_t a_lane = sb + buf * A_STG +
            (uint32_t)((warp_m * 32 + (lane & 15)) * LDS + (lane >> 4) * 8) * 2;
        uint32_t b_lane = sb + 2 * A_STG + buf * B_STG +
            (uint32_t)((warp_n * WNSZ + (lane >> 4) * 8 + (lane & 7)) * LDS +
                       ((lane >> 3) & 1) * 8) * 2;
#pragma unroll
        for (int ks = 0; ks < 4; ks++) {
            uint32_t a[2][4];
            ldsm_x4(a[0], a_lane + ks * 32);
            ldsm_x4(a[1], a_lane + 16 * LDS * 2 + ks * 32);
            uint32_t b[NT / 2][4];
#pragma unroll
            for (int n2 = 0; n2 < NT / 2; n2++)
                ldsm_x4(b[n2], b_lane + n2 * 16 * LDS * 2 + ks * 32);
#pragma unroll
            for (int mt = 0; mt < 2; mt++)
#pragma unroll
                for (int nt = 0; nt < NT; nt++)
                    mma16816(acc[mt][nt], a[mt],
                             b[nt >> 1][(nt & 1) * 2], b[nt >> 1][(nt & 1) * 2 + 1]);
        }
        __syncthreads();
    }

    const int r_base = row0 + warp_m * 32 + (lane >> 2);
    const int c_base = col0 + warp_n * WNSZ + (lane & 3) * 2;
#pragma unroll
    for (int mt = 0; mt < 2; mt++) {
#pragma unroll
        for (int h = 0; h < 2; h++) {
            const int gm = r_base + mt * 16 + h * 8;
            if (MODE == 0) {
                float aq = 0.f, ak = 0.f;
#pragma unroll
                for (int nt = 0; nt < NT; nt++) {
                    int c = c_base + nt * 8;
                    float v0 = acc[mt][nt][h * 2 + 0];
                    float v1 = acc[mt][nt][h * 2 + 1];
                    if (gm < M)
                        *(__half2*)(Ch + (size_t)gm * NTOT + c) = __floats2half2_rn(v0, v1);
                    aq = fmaf(v0, __ldg(qv + c), fmaf(v1, __ldg(qv + c + 1), aq));
                    ak = fmaf(v0, __ldg(kv + c), fmaf(v1, __ldg(kv + c + 1), ak));
                }
                aq += __shfl_xor_sync(0xffffffffu, aq, 1);
                aq += __shfl_xor_sync(0xffffffffu, aq, 2);
                ak += __shfl_xor_sync(0xffffffffu, ak, 1);
                ak += __shfl_xor_sync(0xffffffffu, ak, 2);
                if ((lane & 3) == 0 && gm < M) {
                    atomicAdd(sq + gm, aq);
                    atomicAdd(sk + gm, ak);
                }
            } else if (MODE == 1) {
                if (gm < M) {
#pragma unroll
                    for (int nt = 0; nt < NT; nt++) {
                        int c = c_base + nt * 8;
                        float v0 = fmaxf(acc[mt][nt][h * 2 + 0] + __ldg(bias + c), 0.f);
                        float v1 = fmaxf(acc[mt][nt][h * 2 + 1] + __ldg(bias + c + 1), 0.f);
                        *(__half2*)(Ch + (size_t)gm * NTOT + c) = __floats2half2_rn(v0, v1);
                    }
                }
            } else {  // MODE 2: fused relu + classifier
                float a0 = 0.f, a1 = 0.f;
#pragma unroll
                for (int nt = 0; nt < NT; nt++) {
                    int c = c_base + nt * 8;
                    float t0 = fmaxf(acc[mt][nt][h * 2 + 0] + __ldg(bias + c), 0.f);
                    float t1 = fmaxf(acc[mt][nt][h * 2 + 1] + __ldg(bias + c + 1), 0.f);
                    a0 = fmaf(t0, __ldg(qv + c * 2),     fmaf(t1, __ldg(qv + (c + 1) * 2),     a0));
                    a1 = fmaf(t0, __ldg(qv + c * 2 + 1), fmaf(t1, __ldg(qv + (c + 1) * 2 + 1), a1));
                }
                a0 += __shfl_xor_sync(0xffffffffu, a0, 1);
                a0 += __shfl_xor_sync(0xffffffffu, a0, 2);
                a1 += __shfl_xor_sync(0xffffffffu, a1, 1);
                a1 += __shfl_xor_sync(0xffffffffu, a1, 2);
                if ((lane & 3) == 0 && gm < M) {
                    atomicAdd(Cf + (size_t)gm * 2 + 0, a0);
                    atomicAdd(Cf + (size_t)gm * 2 + 1, a1);
                }
            }
        }
    }
}

// ---------------- prep kernels --------------------------------------------
__global__ void transpose_wt(const float* __restrict__ in, __half* __restrict__ out,
                             int K, int N)
{
    size_t base = (size_t)blockIdx.z * K * N;
    int o = blockIdx.x * 256 + threadIdx.x;
    if (o >= K * N) return;
    int n = o / K, k = o % K;
    out[base + o] = __float2half(in[base + (size_t)k * N + n]);
}

__global__ void f2h4_kernel(const float4* __restrict__ in, __half2* __restrict__ out,
                            size_t n4)
{
    size_t i = (size_t)blockIdx.x * 256 + threadIdx.x;
    if (i >= n4) return;
    float4 v = in[i];
    out[2 * i]     = __floats2half2_rn(v.x, v.y);
    out[2 * i + 1] = __floats2half2_rn(v.z, v.w);
}

__global__ void zero_sqk(float* __restrict__ sq, float* __restrict__ sk)
{
    int i = blockIdx.x * 256 + threadIdx.x;
    if (i < R_REL * N_NODES) { sq[i] = 0.f; sk[i] = 0.f; }
}

__global__ void out_init(float* __restrict__ out, const float* __restrict__ b_cls)
{
    int i = blockIdx.x * 256 + threadIdx.x;
    if (i < N_NODES * 2) out[i] = b_cls[i & 1];
}

// ---------------- CSR build ------------------------------------------------
__global__ void csr_zero(int* __restrict__ deg)
{
    int i = blockIdx.x * 256 + threadIdx.x;
    if (i < N_NODES) deg[i] = 0;
}
__global__ void csr_hist(const int* __restrict__ dst, int* __restrict__ deg)
{
    int e = blockIdx.x * 256 + threadIdx.x;
    if (e < N_EDGES) atomicAdd(&deg[dst[e]], 1);
}
__global__ void csr_scan1(const int* __restrict__ deg, int* __restrict__ excl,
                          int* __restrict__ bsum)
{
    __shared__ int sm[256];
    int t = threadIdx.x, i = blockIdx.x * 256 + t;
    int v = (i < N_NODES) ? deg[i] : 0;
    sm[t] = v;
    __syncthreads();
    for (int off = 1; off < 256; off <<= 1) {
        int x = (t >= off) ? sm[t - off] : 0;
        __syncthreads();
        if (t >= off) sm[t] += x;
        __syncthreads();
    }
    if (i < N_NODES) excl[i] = sm[t] - v;
    if (t == 255) bsum[blockIdx.x] = sm[255];
}
__global__ void csr_scan2(int* __restrict__ bsum)   // single block
{
    __shared__ int sm[256];
    int t = threadIdx.x;
    int v = (t < NBLK_SCAN) ? bsum[t] : 0;
    sm[t] = v;
    __syncthreads();
    for (int off = 1; off < 256; off <<= 1) {
        int x = (t >= off) ? sm[t - off] : 0;
        __syncthreads();
        if (t >= off) sm[t] += x;
        __syncthreads();
    }
    if (t < NBLK_SCAN) bsum[t] = sm[t] - v;
}
__global__ void csr_scan3(const int* __restrict__ excl, const int* __restrict__ bsum,
                          int* __restrict__ rowptr, int* __restrict__ fill)
{
    int i = blockIdx.x * 256 + threadIdx.x;
    if (i < N_NODES) {
        int p = excl[i] + bsum[i >> 8];
        rowptr[i] = p;
        fill[i]   = p;
    }
    if (i == 0) rowptr[N_NODES] = N_EDGES;
}
__global__ void csr_scatter(const int* __restrict__ src, const int* __restrict__ dst,
                            const int* __restrict__ et, int* __restrict__ fill,
                            int* __restrict__ eidx)
{
    int e = blockIdx.x * 256 + threadIdx.x;
    if (e >= N_EDGES) return;
    int pos = atomicAdd(&fill[dst[e]], 1);
    eidx[pos] = src[e] | (et[e] << 16);
}

// ---------------- fused softmax-aggregate: one warp per dst node ----------
// fp16 xw rows: one uint4 (8 halves) per lane covers the whole 256-col row.
__global__ __launch_bounds__(256)
void aggregate_kernel(const int* __restrict__ rowptr, const int* __restrict__ eidx,
                      const float* __restrict__ sq, const float* __restrict__ sk,
                      const __half* __restrict__ xwh, const float* __restrict__ bias,
                      __half* __restrict__ out_h)
{
    const int d    = blockIdx.x * 8 + (threadIdx.x >> 5);
    const int lane = threadIdx.x & 31;
    const int start = rowptr[d], end = rowptr[d + 1];

    const int c0 = lane * 8;            // cols [c0, c0+8)

    if (start == end) {                 // no in-edges: out = bias
        float4 b0 = *(const float4*)(bias + c0);
        float4 b1 = *(const float4*)(bias + c0 + 4);
        __half2 h0 = __floats2half2_rn(b0.x, b0.y), h1 = __floats2half2_rn(b0.z, b0.w);
        __half2 h2 = __floats2half2_rn(b1.x, b1.y), h3 = __floats2half2_rn(b1.z, b1.w);
        *(uint4*)(out_h + (size_t)d * HID + c0) = make_uint4(
            *(uint32_t*)&h0, *(uint32_t*)&h1, *(uint32_t*)&h2, *(uint32_t*)&h3);
        return;
    }

    // pass 1: segment max of leaky_relu scores
    float m = -INFINITY;
    for (int i = start + lane; i < end; i += 32) {
        int pk = eidx[i];
        int s = pk & 0xFFFF, r = pk >> 16;
        float a = __ldg(sq + r * N_NODES + d) + __ldg(sk + r * N_NODES + s);
        a = (a > 0.f) ? a : NEG_SLOPE * a;
        m = fmaxf(m, a);
    }
#pragma unroll
    for (int o = 16; o; o >>= 1) m = fmaxf(m, __shfl_xor_sync(0xffffffffu, m, o));

    // pass 2: gather + unnormalized accumulate, denom alongside
    float acc[8];
#pragma unroll
    for (int j = 0; j < 8; j++) acc[j] = 0.f;
    float dn = 0.f;

    for (int base = start; base < end; base += 32) {
        int i = base + lane;
        float ea = 0.f; int pk = 0;
        if (i < end) {
            pk = eidx[i];
            int s = pk & 0xFFFF, r = pk >> 16;
            float a = __ldg(sq + r * N_NODES + d) + __ldg(sk + r * N_NODES + s);
            a = (a > 0.f) ? a : NEG_SLOPE * a;
            ea = __expf(a - m);
        }
        dn += ea;
        int cnt = min(32, end - base);
        for (int l = 0; l < cnt; l++) {
            float coef = __shfl_sync(0xffffffffu, ea, l);
            int pkl    = __shfl_sync(0xffffffffu, pk, l);
            int s = pkl & 0xFFFF, r = pkl >> 16;
            uint4 v = *(const uint4*)(xwh + ((size_t)r * N_NODES + s) * HID + c0);
            const __half2* hp = (const __half2*)&v;
#pragma unroll
            for (int j = 0; j < 4; j++) {
                float2 f = __half22float2(hp[j]);
                acc[2 * j]     = fmaf(coef, f.x, acc[2 * j]);
                acc[2 * j + 1] = fmaf(coef, f.y, acc[2 * j + 1]);
            }
        }
    }
#pragma unroll
    for (int o = 16; o; o >>= 1) dn += __shfl_xor_sync(0xffffffffu, dn, o);
    float inv = 1.f / (dn + 1e-16f);

    float4 b0 = *(const float4*)(bias + c0);
    float4 b1 = *(const float4*)(bias + c0 + 4);
    __half2 h0 = __floats2half2_rn(fmaf(acc[0], inv, b0.x), fmaf(acc[1], inv, b0.y));
    __half2 h1 = __floats2half2_rn(fmaf(acc[2], inv, b0.z), fmaf(acc[3], inv, b0.w));
    __half2 h2 = __floats2half2_rn(fmaf(acc[4], inv, b1.x), fmaf(acc[5], inv, b1.y));
    __half2 h3 = __floats2half2_rn(fmaf(acc[6], inv, b1.z), fmaf(acc[7], inv, b1.w));
    *(uint4*)(out_h + (size_t)d * HID + c0) = make_uint4(
        *(uint32_t*)&h0, *(uint32_t*)&h1, *(uint32_t*)&h2, *(uint32_t*)&h3);
}

// ---------------- host orchestration --------------------------------------
extern "C" void kernel_launch(void* const* d_in, const int* in_sizes, int n_in,
                              void* d_out, int out_size)
{
    const float* x          = (const float*)d_in[0];
    const int*   edge_index = (const int*)  d_in[1];
    const int*   edge_type  = (const int*)  d_in[2];
    const float* w_in  = (const float*)d_in[3];
    const float* b_in  = (const float*)d_in[4];
    const float* c1w = (const float*)d_in[5];
    const float* c1q = (const float*)d_in[6];
    const float* c1k = (const float*)d_in[7];
    const float* c1b = (const float*)d_in[8];
    const float* c2w = (const float*)d_in[9];
    const float* c2q = (const float*)d_in[10];
    const float* c2k = (const float*)d_in[11];
    const float* c2b = (const float*)d_in[12];
    const float* w_out = (const float*)d_in[13];
    const float* b_out = (const float*)d_in[14];
    const float* w_cls = (const float*)d_in[15];
    const float* b_cls = (const float*)d_in[16];
    float* out = (float*)d_out;

    const int* src = edge_index;
    const int* dst = edge_index + N_EDGES;

    float *p_sq, *p_sk;
    __half *p_xwh, *p_xh, *p_hh, *p_wt, *p_cwt, *p_wot;
    int *p_deg, *p_excl, *p_bsum, *p_rowptr, *p_fill, *p_eidx;
    cudaGetSymbolAddress((void**)&p_xwh, g_xwh);
    cudaGetSymbolAddress((void**)&p_sq,  g_sq);
    cudaGetSymbolAddress((void**)&p_sk,  g_sk);
    cudaGetSymbolAddress((void**)&p_xh,  g_xh);
    cudaGetSymbolAddress((void**)&p_hh,  g_hh);
    cudaGetSymbolAddress((void**)&p_wt,  g_wt);
    cudaGetSymbolAddress((void**)&p_cwt, g_cwt);
    cudaGetSymbolAddress((void**)&p_wot, g_wot);
    cudaGetSymbolAddress((void**)&p_deg,    g_deg);
    cudaGetSymbolAddress((void**)&p_excl,   g_excl);
    cudaGetSymbolAddress((void**)&p_bsum,   g_bsum);
    cudaGetSymbolAddress((void**)&p_rowptr, g_rowptr);
    cudaGetSymbolAddress((void**)&p_fill,   g_fill);
    cudaGetSymbolAddress((void**)&p_eidx,   g_eidx);

    const int SMEM_BIG   = 73728;
    const int SMEM_SMALL = 55296;
    cudaFuncSetAttribute((const void*)gemm_mma<768, 256, 128, 1>,
                         cudaFuncAttributeMaxDynamicSharedMemorySize, SMEM_BIG);
    cudaFuncSetAttribute((const void*)gemm_mma<256, 256, 128, 0>,
                         cudaFuncAttributeMaxDynamicSharedMemorySize, SMEM_BIG);
    cudaFuncSetAttribute((const void*)gemm_mma<256, 64, 64, 2>,
                         cudaFuncAttributeMaxDynamicSharedMemorySize, SMEM_SMALL);

    const int MB = (N_NODES + 127) / 128;   // 391
    const int EB = (N_EDGES + 255) / 256;   // 1250
    const int NB = (N_NODES + 255) / 256;   // 196

    // ---- CSR build (shared by both conv layers) ----
    csr_zero   <<<NB, 256>>>(p_deg);
    csr_hist   <<<EB, 256>>>(dst, p_deg);
    csr_scan1  <<<NB, 256>>>(p_deg, p_excl, p_bsum);
    csr_scan2  <<<1, 256>>>(p_bsum);
    csr_scan3  <<<NB, 256>>>(p_excl, p_bsum, p_rowptr, p_fill);
    csr_scatter<<<EB, 256>>>(src, dst, edge_type, p_fill, p_eidx);

    // ---- prep: fp16 conversions + weight transposes ----
    f2h4_kernel<<<(int)(((size_t)N_NODES * IN_DIM / 4 + 255) / 256), 256>>>(
        (const float4*)x, (__half2*)p_xh, (size_t)N_NODES * IN_DIM / 4);
    transpose_wt<<<dim3((IN_DIM * HID + 255) / 256, 1, 1), 256>>>(w_in, p_wt, IN_DIM, HID);
    transpose_wt<<<dim3((HID * HID + 255) / 256, 1, R_REL), 256>>>(c1w, p_cwt, HID, HID);
    transpose_wt<<<dim3((HID * OUT_DIM + 255) / 256, 1, 1), 256>>>(w_out, p_wot, HID, OUT_DIM);

    // ---- h = relu(x @ w_in + b_in) -> fp16 ----
    gemm_mma<768, 256, 128, 1><<<dim3(MB, 2, 1), 256, SMEM_BIG>>>(
        p_xh, p_wt, b_in, nullptr, nullptr, nullptr, p_hh, nullptr, nullptr, N_NODES);

    // ---- conv1: GEMM (fp16 xw + fused sq/sk) then fused softmax-aggregate
    zero_sqk<<<(R_REL * N_NODES + 255) / 256, 256>>>(p_sq, p_sk);
    gemm_mma<256, 256, 128, 0><<<dim3(MB, 2, R_REL), 256, SMEM_BIG>>>(
        p_hh, p_cwt, nullptr, c1q, c1k, nullptr, p_xwh, p_sq, p_sk, N_NODES);
    aggregate_kernel<<<N_NODES / 8, 256>>>(p_rowptr, p_eidx, p_sq, p_sk, p_xwh, c1b, p_hh);

    // ---- conv2 ----
    transpose_wt<<<dim3((HID * HID + 255) / 256, 1, R_REL), 256>>>(c2w, p_cwt, HID, HID);
    zero_sqk<<<(R_REL * N_NODES + 255) / 256, 256>>>(p_sq, p_sk);
    gemm_mma<256, 256, 128, 0><<<dim3(MB, 2, R_REL), 256, SMEM_BIG>>>(
        p_hh, p_cwt, nullptr, c2q, c2k, nullptr, p_xwh, p_sq, p_sk, N_NODES);
    aggregate_kernel<<<N_NODES / 8, 256>>>(p_rowptr, p_eidx, p_sq, p_sk, p_xwh, c2b, p_hh);

    // ---- head: out = (relu(h @ w_out + b_out)) @ w_cls + b_cls (fully fused)
    out_init<<<(N_NODES * 2 + 255) / 256, 256>>>(out, b_cls);
    gemm_mma<256, 64, 64, 2><<<dim3(MB, 1, 1), 256, SMEM_SMALL>>>(
        p_hh, p_wot, b_out, w_cls, nullptr, out, nullptr, nullptr, nullptr, N_NODES);
}

// round 9
// speedup vs baseline: 4.9440x; 1.0052x over previous
#include <cuda_runtime.h>
#include <cuda_fp16.h>
#include <math.h>
#include <stdint.h>

#define N_NODES 50000
#define N_EDGES 320000
#define R_REL   3
#define IN_DIM  768
#define HID     256
#define OUT_DIM 64
#define NEG_SLOPE 0.2f
#define NBLK_SCAN 196   // ceil(N_NODES/256)

// ---------------- static scratch (no allocations allowed) ----------------
__device__ __half g_xwh[(size_t)R_REL * N_NODES * HID];   // fp16 per-relation transforms (75 MB)
__device__ float  g_sq [R_REL * N_NODES];
__device__ float  g_sk [R_REL * N_NODES];
__device__ __half g_xh [(size_t)N_NODES * IN_DIM];
__device__ __half g_hh [(size_t)N_NODES * HID];
__device__ __half g_wt [IN_DIM * HID];                  // w_in^T  [256][768]
__device__ __half g_cwt [(size_t)R_REL * HID * HID];    // conv1 W^T [r][256][256]
__device__ __half g_cwt2[(size_t)R_REL * HID * HID];    // conv2 W^T [r][256][256]
__device__ __half g_wot[HID * OUT_DIM];                 // w_out^T [64][256]
// CSR scratch
__device__ int g_deg  [N_NODES];
__device__ int g_excl [N_NODES];
__device__ int g_bsum [256];
__device__ int g_rowptr[N_NODES + 1];
__device__ int g_fill [N_NODES];
__device__ int g_eidx [N_EDGES];        // packed (et<<16)|src, sorted by dst

// ================= baseline-ISA helpers (sm_80+ features only) ============
__device__ __forceinline__ uint32_t smem_u32(const void* p) {
    uint32_t a;
    asm("{ .reg .u64 t; cvta.to.shared.u64 t, %1; cvt.u32.u64 %0, t; }" : "=r"(a) : "l"(p));
    return a;
}
#define CP_ASYNC16(dst, src, sz) \
    asm volatile("cp.async.ca.shared.global [%0], [%1], 16, %2;" \
                 :: "r"(dst), "l"(src), "r"(sz))
#define CP_COMMIT() asm volatile("cp.async.commit_group;")
#define CP_WAIT(n)  asm volatile("cp.async.wait_group %0;" :: "n"(n))

__device__ __forceinline__ void ldsm_x4(uint32_t* r, uint32_t addr) {
    asm volatile("ldmatrix.sync.aligned.m8n8.x4.shared.b16 {%0,%1,%2,%3}, [%4];"
                 : "=r"(r[0]), "=r"(r[1]), "=r"(r[2]), "=r"(r[3]) : "r"(addr));
}
__device__ __forceinline__ void mma16816(float* d, const uint32_t* a,
                                         uint32_t b0, uint32_t b1) {
    asm volatile("mma.sync.aligned.m16n8k16.row.col.f32.f16.f16.f32 "
                 "{%0,%1,%2,%3}, {%4,%5,%6,%7}, {%8,%9}, {%0,%1,%2,%3};"
                 : "+f"(d[0]), "+f"(d[1]), "+f"(d[2]), "+f"(d[3])
                 : "r"(a[0]), "r"(a[1]), "r"(a[2]), "r"(a[3]), "r"(b0), "r"(b1));
}

// ================= HMMA GEMM ==============================================
// MODE 0: conv  — fp16 Ch (= xwh, +z strides), fused sq/sk dots (atomicAdd)
// MODE 1: w_in  — bias + relu -> fp16 Ch
// MODE 2: head  — bias + relu + fused classifier -> atomicAdd into Cf(out)
template<int KTOT, int NTOT, int CN, int MODE>
__global__ __launch_bounds__(256, 1)
void gemm_mma(const __half* __restrict__ A, const __half* __restrict__ Bt,
              const float* __restrict__ bias, const float* __restrict__ qv,
              const float* __restrict__ kv, float* __restrict__ Cf,
              __half* __restrict__ Ch, float* __restrict__ sq,
              float* __restrict__ sk, int M)
{
    constexpr int KT    = KTOT / 64;
    constexpr int LDS   = 72;
    constexpr int A_STG = 128 * LDS * 2;
    constexpr int B_STG = CN * LDS * 2;
    constexpr int A_IT  = 128 * 8 / 256;
    constexpr int B_IT  = CN * 8 / 256;
    constexpr int WNSZ  = CN / 2;
    constexpr int NT    = WNSZ / 8;

    extern __shared__ char smem[];
    const uint32_t sb = smem_u32(smem);
    const int tid = threadIdx.x, wid = tid >> 5, lane = tid & 31;
    const int warp_m = wid & 3, warp_n = wid >> 2;
    const int row0 = blockIdx.x * 128;
    const int col0 = blockIdx.y * CN;
    const int z = blockIdx.z;
    const __half* Btz = Bt + (size_t)z * NTOT * KTOT;
    if (MODE == 0) { Ch += (size_t)z * M * NTOT; sq += (size_t)z * M; sk += (size_t)z * M; }

    float acc[2][NT][4];
#pragma unroll
    for (int mt = 0; mt < 2; mt++)
#pragma unroll
        for (int nt = 0; nt < NT; nt++)
#pragma unroll
            for (int j = 0; j < 4; j++) acc[mt][nt][j] = 0.f;

    auto prefetch = [&](int kb) {
        int buf = kb & 1;
        uint32_t abase = sb + buf * A_STG;
#pragma unroll
        for (int i = 0; i < A_IT; i++) {
            int q = tid + i * 256, r = q >> 3, c = q & 7;
            uint32_t dst = abase + (uint32_t)(r * LDS + c * 8) * 2;
            const void* src = A + (size_t)(row0 + r) * KTOT + kb * 64 + c * 8;
            CP_ASYNC16(dst, src, (row0 + r < M) ? 16 : 0);
        }
        uint32_t bbase = sb + 2 * A_STG + buf * B_STG;
#pragma unroll
        for (int i = 0; i < B_IT; i++) {
            int q = tid + i * 256, r = q >> 3, c = q & 7;
            uint32_t dst = bbase + (uint32_t)(r * LDS + c * 8) * 2;
            const void* src = Btz + (size_t)(col0 + r) * KTOT + kb * 64 + c * 8;
            CP_ASYNC16(dst, src, 16);
        }
        CP_COMMIT();
    };

    prefetch(0);
    for (int kb = 0; kb < KT; kb++) {
        if (kb + 1 < KT) { prefetch(kb + 1); CP_WAIT(1); }
        else             { CP_WAIT(0); }
        __syncthreads();

        int buf = kb & 1;
        uint32_t a_lane = sb + buf * A_STG +
            (uint32_t)((warp_m * 32 + (lane & 15)) * LDS + (lane >> 4) * 8) * 2;
        uint32_t b_lane = sb + 2 * A_STG + buf * B_STG +
            (uint32_t)((warp_n * WNSZ + (lane >> 4) * 8 + (lane & 7)) * LDS +
                       ((lane >> 3) & 1) * 8) * 2;
#pragma unroll
        for (int ks = 0; ks < 4; ks++) {
            uint32_t a[2][4];
            ldsm_x4(a[0], a_lane + ks * 32);
            ldsm_x4(a[1], a_lane + 16 * LDS * 2 + ks * 32);
            uint32_t b[NT / 2][4];
#pragma unroll
            for (int n2 = 0; n2 < NT / 2; n2++)
                ldsm_x4(b[n2], b_lane + n2 * 16 * LDS * 2 + ks * 32);
#pragma unroll
            for (int mt = 0; mt < 2; mt++)
#pragma unroll
                for (int nt = 0; nt < NT; nt++)
                    mma16816(acc[mt][nt], a[mt],
                             b[nt >> 1][(nt & 1) * 2], b[nt >> 1][(nt & 1) * 2 + 1]);
        }
        __syncthreads();
    }

    const int r_base = row0 + warp_m * 32 + (lane >> 2);
    const int c_base = col0 + warp_n * WNSZ + (lane & 3) * 2;
#pragma unroll
    for (int mt = 0; mt < 2; mt++) {
#pragma unroll
        for (int h = 0; h < 2; h++) {
            const int gm = r_base + mt * 16 + h * 8;
            if (MODE == 0) {
                float aq = 0.f, ak = 0.f;
#pragma unroll
                for (int nt = 0; nt < NT; nt++) {
                    int c = c_base + nt * 8;
                    float v0 = acc[mt][nt][h * 2 + 0];
                    float v1 = acc[mt][nt][h * 2 + 1];
                    if (gm < M)
                        *(__half2*)(Ch + (size_t)gm * NTOT + c) = __floats2half2_rn(v0, v1);
                    aq = fmaf(v0, __ldg(qv + c), fmaf(v1, __ldg(qv + c + 1), aq));
                    ak = fmaf(v0, __ldg(kv + c), fmaf(v1, __ldg(kv + c + 1), ak));
                }
                aq += __shfl_xor_sync(0xffffffffu, aq, 1);
                aq += __shfl_xor_sync(0xffffffffu, aq, 2);
                ak += __shfl_xor_sync(0xffffffffu, ak, 1);
                ak += __shfl_xor_sync(0xffffffffu, ak, 2);
                if ((lane & 3) == 0 && gm < M) {
                    atomicAdd(sq + gm, aq);
                    atomicAdd(sk + gm, ak);
                }
            } else if (MODE == 1) {
                if (gm < M) {
#pragma unroll
                    for (int nt = 0; nt < NT; nt++) {
                        int c = c_base + nt * 8;
                        float v0 = fmaxf(acc[mt][nt][h * 2 + 0] + __ldg(bias + c), 0.f);
                        float v1 = fmaxf(acc[mt][nt][h * 2 + 1] + __ldg(bias + c + 1), 0.f);
                        *(__half2*)(Ch + (size_t)gm * NTOT + c) = __floats2half2_rn(v0, v1);
                    }
                }
            } else {  // MODE 2: fused relu + classifier
                float a0 = 0.f, a1 = 0.f;
#pragma unroll
                for (int nt = 0; nt < NT; nt++) {
                    int c = c_base + nt * 8;
                    float t0 = fmaxf(acc[mt][nt][h * 2 + 0] + __ldg(bias + c), 0.f);
                    float t1 = fmaxf(acc[mt][nt][h * 2 + 1] + __ldg(bias + c + 1), 0.f);
                    a0 = fmaf(t0, __ldg(qv + c * 2),     fmaf(t1, __ldg(qv + (c + 1) * 2),     a0));
                    a1 = fmaf(t0, __ldg(qv + c * 2 + 1), fmaf(t1, __ldg(qv + (c + 1) * 2 + 1), a1));
                }
                a0 += __shfl_xor_sync(0xffffffffu, a0, 1);
                a0 += __shfl_xor_sync(0xffffffffu, a0, 2);
                a1 += __shfl_xor_sync(0xffffffffu, a1, 1);
                a1 += __shfl_xor_sync(0xffffffffu, a1, 2);
                if ((lane & 3) == 0 && gm < M) {
                    atomicAdd(Cf + (size_t)gm * 2 + 0, a0);
                    atomicAdd(Cf + (size_t)gm * 2 + 1, a1);
                }
            }
        }
    }
}

// ---------------- prep kernels --------------------------------------------
__global__ void transpose_wt(const float* __restrict__ in, __half* __restrict__ out,
                             int K, int N)
{
    size_t base = (size_t)blockIdx.z * K * N;
    int o = blockIdx.x * 256 + threadIdx.x;
    if (o >= K * N) return;
    int n = o / K, k = o % K;
    out[base + o] = __float2half(in[base + (size_t)k * N + n]);
}

__global__ void f2h4_kernel(const float4* __restrict__ in, __half2* __restrict__ out,
                            size_t n4)
{
    size_t i = (size_t)blockIdx.x * 256 + threadIdx.x;
    if (i >= n4) return;
    float4 v = in[i];
    out[2 * i]     = __floats2half2_rn(v.x, v.y);
    out[2 * i + 1] = __floats2half2_rn(v.z, v.w);
}

__global__ void zero_sqk(float* __restrict__ sq, float* __restrict__ sk)
{
    int i = blockIdx.x * 256 + threadIdx.x;
    if (i < R_REL * N_NODES) { sq[i] = 0.f; sk[i] = 0.f; }
}

__global__ void out_init(float* __restrict__ out, const float* __restrict__ b_cls)
{
    int i = blockIdx.x * 256 + threadIdx.x;
    if (i < N_NODES * 2) out[i] = b_cls[i & 1];
}

// ---------------- CSR build ------------------------------------------------
__global__ void csr_zero(int* __restrict__ deg)
{
    int i = blockIdx.x * 256 + threadIdx.x;
    if (i < N_NODES) deg[i] = 0;
}
__global__ void csr_hist(const int* __restrict__ dst, int* __restrict__ deg)
{
    int e = blockIdx.x * 256 + threadIdx.x;
    if (e < N_EDGES) atomicAdd(&deg[dst[e]], 1);
}
__global__ void csr_scan1(const int* __restrict__ deg, int* __restrict__ excl,
                          int* __restrict__ bsum)
{
    __shared__ int sm[256];
    int t = threadIdx.x, i = blockIdx.x * 256 + t;
    int v = (i < N_NODES) ? deg[i] : 0;
    sm[t] = v;
    __syncthreads();
    for (int off = 1; off < 256; off <<= 1) {
        int x = (t >= off) ? sm[t - off] : 0;
        __syncthreads();
        if (t >= off) sm[t] += x;
        __syncthreads();
    }
    if (i < N_NODES) excl[i] = sm[t] - v;
    if (t == 255) bsum[blockIdx.x] = sm[255];
}
__global__ void csr_scan2(int* __restrict__ bsum)   // single block
{
    __shared__ int sm[256];
    int t = threadIdx.x;
    int v = (t < NBLK_SCAN) ? bsum[t] : 0;
    sm[t] = v;
    __syncthreads();
    for (int off = 1; off < 256; off <<= 1) {
        int x = (t >= off) ? sm[t - off] : 0;
        __syncthreads();
        if (t >= off) sm[t] += x;
        __syncthreads();
    }
    if (t < NBLK_SCAN) bsum[t] = sm[t] - v;
}
__global__ void csr_scan3(const int* __restrict__ excl, const int* __restrict__ bsum,
                          int* __restrict__ rowptr, int* __restrict__ fill)
{
    int i = blockIdx.x * 256 + threadIdx.x;
    if (i < N_NODES) {
        int p = excl[i] + bsum[i >> 8];
        rowptr[i] = p;
        fill[i]   = p;
    }
    if (i == 0) rowptr[N_NODES] = N_EDGES;
}
__global__ void csr_scatter(const int* __restrict__ src, const int* __restrict__ dst,
                            const int* __restrict__ et, int* __restrict__ fill,
                            int* __restrict__ eidx)
{
    int e = blockIdx.x * 256 + threadIdx.x;
    if (e >= N_EDGES) return;
    int pos = atomicAdd(&fill[dst[e]], 1);
    eidx[pos] = src[e] | (et[e] << 16);
}

// ---------------- fused softmax-aggregate: one warp per dst node ----------
// Fast path (deg<=32): single pass, scores kept in registers, grouped gather
// loads (MLP=4). General path: two passes with grouped loads.
__global__ __launch_bounds__(256)
void aggregate_kernel(const int* __restrict__ rowptr, const int* __restrict__ eidx,
                      const float* __restrict__ sq, const float* __restrict__ sk,
                      const __half* __restrict__ xwh, const float* __restrict__ bias,
                      __half* __restrict__ out_h)
{
    const int d    = blockIdx.x * 8 + (threadIdx.x >> 5);
    const int lane = threadIdx.x & 31;
    const int start = rowptr[d], end = rowptr[d + 1];
    const int deg = end - start;
    const int c0 = lane * 8;

    float acc[8] = {0.f, 0.f, 0.f, 0.f, 0.f, 0.f, 0.f, 0.f};
    float dn = 0.f;

    auto gather_group = [&](float ea, int pk, int l0, int cnt) {
        int kc = cnt - l0; if (kc > 4) kc = 4;
        float cf[4]; uint4 v[4];
#pragma unroll
        for (int j = 0; j < 4; j++) {
            if (j < kc) {
                cf[j] = __shfl_sync(0xffffffffu, ea, l0 + j);
                int pkl = __shfl_sync(0xffffffffu, pk, l0 + j);
                int s = pkl & 0xFFFF, r = pkl >> 16;
                v[j] = *(const uint4*)(xwh + ((size_t)r * N_NODES + s) * HID + c0);
            }
        }
#pragma unroll
        for (int j = 0; j < 4; j++) {
            if (j < kc) {
                const __half2* hp = (const __half2*)&v[j];
#pragma unroll
                for (int q = 0; q < 4; q++) {
                    float2 f = __half22float2(hp[q]);
                    acc[2 * q]     = fmaf(cf[j], f.x, acc[2 * q]);
                    acc[2 * q + 1] = fmaf(cf[j], f.y, acc[2 * q + 1]);
                }
            }
        }
    };

    if (deg > 0 && deg <= 32) {
        int i = start + lane;
        int pk = 0; float a = -INFINITY;
        if (i < end) {
            pk = eidx[i];
            int s = pk & 0xFFFF, r = pk >> 16;
            a = __ldg(sq + r * N_NODES + d) + __ldg(sk + r * N_NODES + s);
            a = (a > 0.f) ? a : NEG_SLOPE * a;
        }
        float m = a;
#pragma unroll
        for (int o = 16; o; o >>= 1) m = fmaxf(m, __shfl_xor_sync(0xffffffffu, m, o));
        float ea = (i < end) ? __expf(a - m) : 0.f;
        dn = ea;
#pragma unroll
        for (int o = 16; o; o >>= 1) dn += __shfl_xor_sync(0xffffffffu, dn, o);
        for (int l0 = 0; l0 < deg; l0 += 4) gather_group(ea, pk, l0, deg);
    } else if (deg > 32) {
        float m = -INFINITY;
        for (int i = start + lane; i < end; i += 32) {
            int pk = eidx[i];
            int s = pk & 0xFFFF, r = pk >> 16;
            float a = __ldg(sq + r * N_NODES + d) + __ldg(sk + r * N_NODES + s);
            a = (a > 0.f) ? a : NEG_SLOPE * a;
            m = fmaxf(m, a);
        }
#pragma unroll
        for (int o = 16; o; o >>= 1) m = fmaxf(m, __shfl_xor_sync(0xffffffffu, m, o));

        for (int base = start; base < end; base += 32) {
            int i = base + lane;
            float ea = 0.f; int pk = 0;
            if (i < end) {
                pk = eidx[i];
                int s = pk & 0xFFFF, r = pk >> 16;
                float a = __ldg(sq + r * N_NODES + d) + __ldg(sk + r * N_NODES + s);
                a = (a > 0.f) ? a : NEG_SLOPE * a;
                ea = __expf(a - m);
            }
            dn += ea;
            int cnt = end - base; if (cnt > 32) cnt = 32;
            for (int l0 = 0; l0 < cnt; l0 += 4) gather_group(ea, pk, l0, cnt);
        }
#pragma unroll
        for (int o = 16; o; o >>= 1) dn += __shfl_xor_sync(0xffffffffu, dn, o);
    }

    float inv = (deg > 0) ? 1.f / (dn + 1e-16f) : 0.f;
    float4 b0 = *(const float4*)(bias + c0);
    float4 b1 = *(const float4*)(bias + c0 + 4);
    __half2 h0 = __floats2half2_rn(fmaf(acc[0], inv, b0.x), fmaf(acc[1], inv, b0.y));
    __half2 h1 = __floats2half2_rn(fmaf(acc[2], inv, b0.z), fmaf(acc[3], inv, b0.w));
    __half2 h2 = __floats2half2_rn(fmaf(acc[4], inv, b1.x), fmaf(acc[5], inv, b1.y));
    __half2 h3 = __floats2half2_rn(fmaf(acc[6], inv, b1.z), fmaf(acc[7], inv, b1.w));
    *(uint4*)(out_h + (size_t)d * HID + c0) = make_uint4(
        *(uint32_t*)&h0, *(uint32_t*)&h1, *(uint32_t*)&h2, *(uint32_t*)&h3);
}

// ---------------- host orchestration --------------------------------------
extern "C" void kernel_launch(void* const* d_in, const int* in_sizes, int n_in,
                              void* d_out, int out_size)
{
    const float* x          = (const float*)d_in[0];
    const int*   edge_index = (const int*)  d_in[1];
    const int*   edge_type  = (const int*)  d_in[2];
    const float* w_in  = (const float*)d_in[3];
    const float* b_in  = (const float*)d_in[4];
    const float* c1w = (const float*)d_in[5];
    const float* c1q = (const float*)d_in[6];
    const float* c1k = (const float*)d_in[7];
    const float* c1b = (const float*)d_in[8];
    const float* c2w = (const float*)d_in[9];
    const float* c2q = (const float*)d_in[10];
    const float* c2k = (const float*)d_in[11];
    const float* c2b = (const float*)d_in[12];
    const float* w_out = (const float*)d_in[13];
    const float* b_out = (const float*)d_in[14];
    const float* w_cls = (const float*)d_in[15];
    const float* b_cls = (const float*)d_in[16];
    float* out = (float*)d_out;

    const int* src = edge_index;
    const int* dst = edge_index + N_EDGES;

    float *p_sq, *p_sk;
    __half *p_xwh, *p_xh, *p_hh, *p_wt, *p_cwt, *p_cwt2, *p_wot;
    int *p_deg, *p_excl, *p_bsum, *p_rowptr, *p_fill, *p_eidx;
    cudaGetSymbolAddress((void**)&p_xwh,  g_xwh);
    cudaGetSymbolAddress((void**)&p_sq,   g_sq);
    cudaGetSymbolAddress((void**)&p_sk,   g_sk);
    cudaGetSymbolAddress((void**)&p_xh,   g_xh);
    cudaGetSymbolAddress((void**)&p_hh,   g_hh);
    cudaGetSymbolAddress((void**)&p_wt,   g_wt);
    cudaGetSymbolAddress((void**)&p_cwt,  g_cwt);
    cudaGetSymbolAddress((void**)&p_cwt2, g_cwt2);
    cudaGetSymbolAddress((void**)&p_wot,  g_wot);
    cudaGetSymbolAddress((void**)&p_deg,    g_deg);
    cudaGetSymbolAddress((void**)&p_excl,   g_excl);
    cudaGetSymbolAddress((void**)&p_bsum,   g_bsum);
    cudaGetSymbolAddress((void**)&p_rowptr, g_rowptr);
    cudaGetSymbolAddress((void**)&p_fill,   g_fill);
    cudaGetSymbolAddress((void**)&p_eidx,   g_eidx);

    const int SMEM_BIG   = 73728;
    const int SMEM_SMALL = 55296;
    cudaFuncSetAttribute((const void*)gemm_mma<768, 256, 128, 1>,
                         cudaFuncAttributeMaxDynamicSharedMemorySize, SMEM_BIG);
    cudaFuncSetAttribute((const void*)gemm_mma<256, 256, 128, 0>,
                         cudaFuncAttributeMaxDynamicSharedMemorySize, SMEM_BIG);
    cudaFuncSetAttribute((const void*)gemm_mma<256, 64, 64, 2>,
                         cudaFuncAttributeMaxDynamicSharedMemorySize, SMEM_SMALL);

    // ---- side streams, forked off the capture-origin stream via events ----
    static cudaStream_t s1 = nullptr, s2 = nullptr;
    static cudaEvent_t evRoot = nullptr, evCSR = nullptr, evPrep = nullptr;
    if (s1 == nullptr) {
        cudaStreamCreateWithFlags(&s1, cudaStreamNonBlocking);
        cudaStreamCreateWithFlags(&s2, cudaStreamNonBlocking);
        cudaEventCreateWithFlags(&evRoot, cudaEventDisableTiming);
        cudaEventCreateWithFlags(&evCSR,  cudaEventDisableTiming);
        cudaEventCreateWithFlags(&evPrep, cudaEventDisableTiming);
    }

    const int MB = (N_NODES + 127) / 128;   // 391
    const int EB = (N_EDGES + 255) / 256;   // 1250
    const int NB = (N_NODES + 255) / 256;   // 196

    cudaEventRecord(evRoot, 0);
    cudaStreamWaitEvent(s1, evRoot, 0);
    cudaStreamWaitEvent(s2, evRoot, 0);

    // ---- s1: CSR build (needed only before aggregate1) ----
    csr_zero   <<<NB, 256, 0, s1>>>(p_deg);
    csr_hist   <<<EB, 256, 0, s1>>>(dst, p_deg);
    csr_scan1  <<<NB, 256, 0, s1>>>(p_deg, p_excl, p_bsum);
    csr_scan2  <<<1,  256, 0, s1>>>(p_bsum);
    csr_scan3  <<<NB, 256, 0, s1>>>(p_excl, p_bsum, p_rowptr, p_fill);
    csr_scatter<<<EB, 256, 0, s1>>>(src, dst, edge_type, p_fill, p_eidx);
    cudaEventRecord(evCSR, s1);

    // ---- s2: weight transposes + zeros (needed only before conv1 GEMM) ----
    transpose_wt<<<dim3((HID * HID + 255) / 256, 1, R_REL), 256, 0, s2>>>(c1w, p_cwt, HID, HID);
    transpose_wt<<<dim3((HID * HID + 255) / 256, 1, R_REL), 256, 0, s2>>>(c2w, p_cwt2, HID, HID);
    transpose_wt<<<dim3((HID * OUT_DIM + 255) / 256, 1, 1), 256, 0, s2>>>(w_out, p_wot, HID, OUT_DIM);
    zero_sqk<<<(R_REL * N_NODES + 255) / 256, 256, 0, s2>>>(p_sq, p_sk);
    out_init<<<(N_NODES * 2 + 255) / 256, 256, 0, s2>>>(out, b_cls);
    cudaEventRecord(evPrep, s2);

    // ---- main: x->fp16, w_in^T, w_in GEMM ----
    f2h4_kernel<<<(int)(((size_t)N_NODES * IN_DIM / 4 + 255) / 256), 256>>>(
        (const float4*)x, (__half2*)p_xh, (size_t)N_NODES * IN_DIM / 4);
    transpose_wt<<<dim3((IN_DIM * HID + 255) / 256, 1, 1), 256>>>(w_in, p_wt, IN_DIM, HID);
    gemm_mma<768, 256, 128, 1><<<dim3(MB, 2, 1), 256, SMEM_BIG>>>(
        p_xh, p_wt, b_in, nullptr, nullptr, nullptr, p_hh, nullptr, nullptr, N_NODES);

    // ---- conv1 ----
    cudaStreamWaitEvent(0, evPrep, 0);
    gemm_mma<256, 256, 128, 0><<<dim3(MB, 2, R_REL), 256, SMEM_BIG>>>(
        p_hh, p_cwt, nullptr, c1q, c1k, nullptr, p_xwh, p_sq, p_sk, N_NODES);
    cudaStreamWaitEvent(0, evCSR, 0);
    aggregate_kernel<<<N_NODES / 8, 256>>>(p_rowptr, p_eidx, p_sq, p_sk, p_xwh, c1b, p_hh);

    // ---- conv2 ----
    zero_sqk<<<(R_REL * N_NODES + 255) / 256, 256>>>(p_sq, p_sk);
    gemm_mma<256, 256, 128, 0><<<dim3(MB, 2, R_REL), 256, SMEM_BIG>>>(
        p_hh, p_cwt2, nullptr, c2q, c2k, nullptr, p_xwh, p_sq, p_sk, N_NODES);
    aggregate_kernel<<<N_NODES / 8, 256>>>(p_rowptr, p_eidx, p_sq, p_sk, p_xwh, c2b, p_hh);

    // ---- head: out = (relu(h @ w_out + b_out)) @ w_cls + b_cls (fully fused)
    gemm_mma<256, 64, 64, 2><<<dim3(MB, 1, 1), 256, SMEM_SMALL>>>(
        p_hh, p_wot, b_out, w_cls, nullptr, out, nullptr, nullptr, nullptr, N_NODES);
}